// round 3
// baseline (speedup 1.0000x reference)
#include <cuda_runtime.h>

// TemporalViewModel GRU, R3: two-kernel split.
//  K1: gx[t][g][n] = (x_t @ Wih^T)[n][g]   — non-recurrent GEMM, high occupancy,
//      4 seqs/thread (1 LDS : 8 FFMA2), coalesced STG.128, output TRANSPOSED so
//      K2 reads it with coalesced scalar LDGs.
//  K2: the 24-step recurrence, hh-projection only. 1 seq/thread -> 2048 warps
//      (13.8/SM, 2x R2 occupancy), half the per-warp FMA work of R2.

namespace {
constexpr int T_STEPS = 24;
constexpr int NSEQ    = 65536;            // B*X*Y
constexpr int S = 16, M = 8, C = 8;
constexpr int F = 32, H = 32, G = 96;
constexpr size_t PLANE = (size_t)NSEQ;    // one (t,g) plane of gx
}

typedef unsigned long long u64;

// 604 MB scratch for gx, laid out [T][G][N]
__device__ float g_gx[(size_t)T_STEPS * G * NSEQ];

__device__ __forceinline__ u64 pk2(float lo, float hi) {
    u64 d; asm("mov.b64 %0, {%1, %2};" : "=l"(d) : "f"(lo), "f"(hi)); return d;
}
__device__ __forceinline__ float hsum2(u64 a) {
    float lo, hi;
    asm("mov.b64 {%0, %1}, %2;" : "=f"(lo), "=f"(hi) : "l"(a));
    return lo + hi;
}
__device__ __forceinline__ float lane2(u64 a, int hi_lane) {
    float lo, hi;
    asm("mov.b64 {%0, %1}, %2;" : "=f"(lo), "=f"(hi) : "l"(a));
    return hi_lane ? hi : lo;
}
__device__ __forceinline__ u64 fma2(u64 a, u64 b, u64 c) {
    u64 d; asm("fma.rn.f32x2 %0, %1, %2, %3;" : "=l"(d) : "l"(a), "l"(b), "l"(c));
    return d;
}
__device__ __forceinline__ float sigm(float x) {
    return __fdividef(1.f, 1.f + __expf(-x));
}
__device__ __forceinline__ float tanh_fast(float x) {
    return __fdividef(2.f, 1.f + __expf(-2.f * x)) - 1.f;
}

// load x = concat(spatial[16], met[8], ctx[8]) for sequence n, step t; K-pair packed
__device__ __forceinline__ void load_x(const float* __restrict__ spatial,
                                       const float* __restrict__ met,
                                       const float* __restrict__ ctx,
                                       int t, int n, u64* x2) {
    const float4* sp = reinterpret_cast<const float4*>(spatial + ((size_t)t * NSEQ + n) * S);
    const float4* mp = reinterpret_cast<const float4*>(met     + ((size_t)t * NSEQ + n) * M);
    const float4* cp = reinterpret_cast<const float4*>(ctx     + ((size_t)t * NSEQ + n) * C);
    float4 v;
    #pragma unroll
    for (int q = 0; q < 4; q++) {
        v = sp[q];
        x2[2 * q]     = pk2(v.x, v.y);
        x2[2 * q + 1] = pk2(v.z, v.w);
    }
    #pragma unroll
    for (int q = 0; q < 2; q++) {
        v = mp[q];
        x2[8 + 2 * q] = pk2(v.x, v.y);
        x2[9 + 2 * q] = pk2(v.z, v.w);
    }
    #pragma unroll
    for (int q = 0; q < 2; q++) {
        v = cp[q];
        x2[12 + 2 * q] = pk2(v.x, v.y);
        x2[13 + 2 * q] = pk2(v.z, v.w);
    }
}

// ---------------- Kernel 1: input projection (pure GEMM, transposed output) --
// grid: (NSEQ/256, T).  block: 64 threads, each handles 4 consecutive seqs.
__global__ void __launch_bounds__(64)
gx_kernel(const float* __restrict__ spatial,
          const float* __restrict__ met,
          const float* __restrict__ ctx,
          const float* __restrict__ Wih)       // (96, 32)
{
    __shared__ __align__(16) float sW[G * F];
    for (int i = threadIdx.x; i < G * F; i += blockDim.x) sW[i] = Wih[i];
    __syncthreads();

    const int t  = blockIdx.y;
    const int n0 = blockIdx.x * 256 + threadIdx.x * 4;   // 4 consecutive seqs

    u64 x2[4][F / 2];
    #pragma unroll
    for (int q = 0; q < 4; q++) load_x(spatial, met, ctx, t, n0 + q, x2[q]);

    float* gbase = g_gx + (size_t)t * G * NSEQ + n0;

    #pragma unroll 2
    for (int g = 0; g < G; g++) {
        const ulonglong2* wr = reinterpret_cast<const ulonglong2*>(sW + g * F);
        u64 a0 = 0, a1 = 0, a2 = 0, a3 = 0;
        #pragma unroll
        for (int k = 0; k < F / 4; k++) {
            ulonglong2 w = wr[k];
            a0 = fma2(w.x, x2[0][2 * k], a0); a0 = fma2(w.y, x2[0][2 * k + 1], a0);
            a1 = fma2(w.x, x2[1][2 * k], a1); a1 = fma2(w.y, x2[1][2 * k + 1], a1);
            a2 = fma2(w.x, x2[2][2 * k], a2); a2 = fma2(w.y, x2[2][2 * k + 1], a2);
            a3 = fma2(w.x, x2[3][2 * k], a3); a3 = fma2(w.y, x2[3][2 * k + 1], a3);
        }
        float4 o = make_float4(hsum2(a0), hsum2(a1), hsum2(a2), hsum2(a3));
        *reinterpret_cast<float4*>(gbase + (size_t)g * PLANE) = o;   // STG.128, coalesced
    }
}

// ---------------- Kernel 2: recurrence (hh projection only) ------------------
// grid: NSEQ/64. block: 64 threads, 1 seq/thread.
__global__ void __launch_bounds__(64, 7)
gru_rec_kernel(const float* __restrict__ Whh,   // (96, 32)
               const float* __restrict__ bih,   // (96,)
               const float* __restrict__ bhh,   // (96,)
               const float* __restrict__ Wout,  // (32, 16)
               float* __restrict__ out)         // (N, 16)
{
    __shared__ __align__(16) float sWhh[G * H];
    __shared__ float sBr[H], sBz[H], sBnx[H], sBnh[H];
    __shared__ __align__(16) float sWo[H * S];

    for (int i = threadIdx.x; i < G * H; i += blockDim.x) sWhh[i] = Whh[i];
    for (int i = threadIdx.x; i < H; i += blockDim.x) {
        sBr[i]  = bih[i] + bhh[i];
        sBz[i]  = bih[H + i] + bhh[H + i];
        sBnx[i] = bih[2 * H + i];
        sBnh[i] = bhh[2 * H + i];
    }
    for (int i = threadIdx.x; i < H * S; i += blockDim.x) sWo[i] = Wout[i];
    __syncthreads();

    const int n = blockIdx.x * blockDim.x + threadIdx.x;

    u64 h2[H / 2];
    #pragma unroll
    for (int i = 0; i < H / 2; i++) h2[i] = 0ull;
    float hnew[H];

    #pragma unroll 1
    for (int t = 0; t < T_STEPS; t++) {
        const float* gxt = g_gx + (size_t)t * G * NSEQ + n;

        // prefetch j = 0 trio (coalesced scalar LDGs)
        float fr = __ldg(gxt);
        float fz = __ldg(gxt + (size_t)H * PLANE);
        float fn = __ldg(gxt + (size_t)(2 * H) * PLANE);

        #pragma unroll 1
        for (int j = 0; j < H; j++) {
            const float cr = fr, cz = fz, cn = fn;
            // prefetch j+1 (clamped; planes j..2H+31 stay in-bounds)
            const int jn = (j < H - 1) ? j + 1 : j;
            fr = __ldg(gxt + (size_t)jn * PLANE);
            fz = __ldg(gxt + (size_t)(H + jn) * PLANE);
            fn = __ldg(gxt + (size_t)(2 * H + jn) * PLANE);

            const ulonglong2* ur = reinterpret_cast<const ulonglong2*>(sWhh + j * H);
            const ulonglong2* uz = reinterpret_cast<const ulonglong2*>(sWhh + (j + H) * H);
            const ulonglong2* un = reinterpret_cast<const ulonglong2*>(sWhh + (j + 2 * H) * H);

            u64 br = 0, bz = 0, bn = 0;
            #pragma unroll
            for (int k = 0; k < H / 4; k++) {
                const u64 hL = h2[2 * k], hH = h2[2 * k + 1];
                ulonglong2 w;
                w = ur[k]; br = fma2(w.x, hL, br); br = fma2(w.y, hH, br);
                w = uz[k]; bz = fma2(w.x, hL, bz); bz = fma2(w.y, hH, bz);
                w = un[k]; bn = fma2(w.x, hL, bn); bn = fma2(w.y, hH, bn);
            }

            float gr  = hsum2(br) + cr + sBr[j];
            float gz  = hsum2(bz) + cz + sBz[j];
            float gxn = cn + sBnx[j];
            float ghn = hsum2(bn) + sBnh[j];

            float r  = sigm(gr);
            float z  = sigm(gz);
            float nn = tanh_fast(fmaf(r, ghn, gxn));
            float hold = lane2(h2[j >> 1], j & 1);
            hnew[j] = fmaf(z, hold - nn, nn);
        }

        #pragma unroll
        for (int i = 0; i < H / 2; i++) h2[i] = pk2(hnew[2 * i], hnew[2 * i + 1]);
    }

    // output projection: out[n,:] = h_final @ W (32x16)
    float acc[S];
    #pragma unroll
    for (int s = 0; s < S; s++) acc[s] = 0.f;
    #pragma unroll
    for (int k = 0; k < H; k++) {
        const float hk = hnew[k];
        #pragma unroll
        for (int s = 0; s < S; s++) acc[s] = fmaf(hk, sWo[k * S + s], acc[s]);
    }
    float4* op = reinterpret_cast<float4*>(out + (size_t)n * S);
    #pragma unroll
    for (int q = 0; q < 4; q++)
        op[q] = make_float4(acc[4 * q], acc[4 * q + 1], acc[4 * q + 2], acc[4 * q + 3]);
}

extern "C" void kernel_launch(void* const* d_in, const int* in_sizes, int n_in,
                              void* d_out, int out_size) {
    (void)in_sizes; (void)n_in; (void)out_size;
    const float* spatial = (const float*)d_in[0];
    const float* met     = (const float*)d_in[1];
    const float* ctx     = (const float*)d_in[2];
    const float* Wih     = (const float*)d_in[3];
    const float* Whh     = (const float*)d_in[4];
    const float* bih     = (const float*)d_in[5];
    const float* bhh     = (const float*)d_in[6];
    const float* Wo      = (const float*)d_in[7];
    float* out           = (float*)d_out;

    dim3 g1(NSEQ / 256, T_STEPS);
    gx_kernel<<<g1, 64>>>(spatial, met, ctx, Wih);
    gru_rec_kernel<<<NSEQ / 64, 64>>>(Whh, bih, bhh, Wo, out);
}

// round 4
// speedup vs baseline: 1.4089x; 1.4089x over previous
#include <cuda_runtime.h>

// TemporalViewModel GRU, R4: fused single kernel (R2 base, split reverted).
// 2 sequences/thread; packed f32x2 FMAs for all dot products.
// NEW: activations via hardware MUFU tanh.approx (1 MUFU per gate instead of
// exp+rcp chains -> MUFU pipe load halved, per-gate latency chain ~4x shorter),
// biases folded into packed accumulator init, per-j biases as one LDS.128.

namespace {
constexpr int T_STEPS = 24;
constexpr int NSEQ    = 65536;   // B*X*Y
constexpr int HALF    = NSEQ / 2;
constexpr int S       = 16;
constexpr int M       = 8;
constexpr int C       = 8;
constexpr int F       = 32;
constexpr int H       = 32;
constexpr int G       = 96;
}

typedef unsigned long long u64;

__device__ __forceinline__ u64 pk2(float lo, float hi) {
    u64 d; asm("mov.b64 %0, {%1, %2};" : "=l"(d) : "f"(lo), "f"(hi)); return d;
}
__device__ __forceinline__ float hsum2(u64 a) {
    float lo, hi;
    asm("mov.b64 {%0, %1}, %2;" : "=f"(lo), "=f"(hi) : "l"(a));
    return lo + hi;
}
__device__ __forceinline__ float lane2(u64 a, int hi_lane) {
    float lo, hi;
    asm("mov.b64 {%0, %1}, %2;" : "=f"(lo), "=f"(hi) : "l"(a));
    return hi_lane ? hi : lo;
}
__device__ __forceinline__ u64 fma2(u64 a, u64 b, u64 c) {
    u64 d; asm("fma.rn.f32x2 %0, %1, %2, %3;" : "=l"(d) : "l"(a), "l"(b), "l"(c));
    return d;
}
__device__ __forceinline__ u64 add2(u64 a, u64 b) {
    u64 d; asm("add.rn.f32x2 %0, %1, %2;" : "=l"(d) : "l"(a), "l"(b));
    return d;
}
// hardware MUFU tanh (sm_75+): 1 MUFU op, max abs err ~1e-5
__device__ __forceinline__ float tanh_hw(float x) {
    float y; asm("tanh.approx.f32 %0, %1;" : "=f"(y) : "f"(x)); return y;
}
// sigmoid(x) = 0.5*tanh(0.5x) + 0.5  -> FMUL + MUFU + FFMA
__device__ __forceinline__ float sigm_hw(float x) {
    return fmaf(0.5f, tanh_hw(0.5f * x), 0.5f);
}

// load x = concat(spatial[16], met[8], ctx[8]) for sequence n at step t, K-pair packed
__device__ __forceinline__ void load_x(const float* __restrict__ spatial,
                                       const float* __restrict__ met,
                                       const float* __restrict__ ctx,
                                       int t, int n, u64* x2) {
    const float4* sp = reinterpret_cast<const float4*>(spatial + ((size_t)t * NSEQ + n) * S);
    const float4* mp = reinterpret_cast<const float4*>(met     + ((size_t)t * NSEQ + n) * M);
    const float4* cp = reinterpret_cast<const float4*>(ctx     + ((size_t)t * NSEQ + n) * C);
    float4 v;
    #pragma unroll
    for (int q = 0; q < 4; q++) {
        v = sp[q];
        x2[2 * q]     = pk2(v.x, v.y);
        x2[2 * q + 1] = pk2(v.z, v.w);
    }
    #pragma unroll
    for (int q = 0; q < 2; q++) {
        v = mp[q];
        x2[8 + 2 * q] = pk2(v.x, v.y);
        x2[9 + 2 * q] = pk2(v.z, v.w);
    }
    #pragma unroll
    for (int q = 0; q < 2; q++) {
        v = cp[q];
        x2[12 + 2 * q] = pk2(v.x, v.y);
        x2[13 + 2 * q] = pk2(v.z, v.w);
    }
}

__global__ void __launch_bounds__(64, 4)
gru_fused4_kernel(const float* __restrict__ spatial,
                  const float* __restrict__ met,
                  const float* __restrict__ ctx,
                  const float* __restrict__ Wih,   // (96, 32)
                  const float* __restrict__ Whh,   // (96, 32)
                  const float* __restrict__ bih,   // (96,)
                  const float* __restrict__ bhh,   // (96,)
                  const float* __restrict__ Wout,  // (32, 16)
                  float* __restrict__ out)         // (N, 16)
{
    __shared__ __align__(16) float sWih[G * F];
    __shared__ __align__(16) float sWhh[G * H];
    __shared__ __align__(16) float sBias[H * 4];   // per j: (br, bz, bnx, bnh)
    __shared__ __align__(16) float sWo[H * S];

    for (int i = threadIdx.x; i < G * F; i += blockDim.x) sWih[i] = Wih[i];
    for (int i = threadIdx.x; i < G * H; i += blockDim.x) sWhh[i] = Whh[i];
    for (int i = threadIdx.x; i < H; i += blockDim.x) {
        sBias[4 * i + 0] = bih[i] + bhh[i];                 // r
        sBias[4 * i + 1] = bih[H + i] + bhh[H + i];         // z
        sBias[4 * i + 2] = bih[2 * H + i];                  // n (input side)
        sBias[4 * i + 3] = bhh[2 * H + i];                  // n (hidden side)
    }
    for (int i = threadIdx.x; i < H * S; i += blockDim.x) sWo[i] = Wout[i];
    __syncthreads();

    const int n0 = blockIdx.x * blockDim.x + threadIdx.x;   // 0..32767
    const int n1 = n0 + HALF;                               // 32768..65535

    u64 ha2[H / 2], hb2[H / 2];
    #pragma unroll
    for (int i = 0; i < H / 2; i++) { ha2[i] = 0ull; hb2[i] = 0ull; }
    float hna[H], hnb[H];

    #pragma unroll 1
    for (int t = 0; t < T_STEPS; t++) {
        u64 xa2[F / 2], xb2[F / 2];
        load_x(spatial, met, ctx, t, n0, xa2);
        load_x(spatial, met, ctx, t, n1, xb2);

        #pragma unroll 1
        for (int j = 0; j < H; j++) {
            const ulonglong2* wr = reinterpret_cast<const ulonglong2*>(sWih + j * F);
            const ulonglong2* wz = reinterpret_cast<const ulonglong2*>(sWih + (j + H) * F);
            const ulonglong2* wn = reinterpret_cast<const ulonglong2*>(sWih + (j + 2 * H) * F);
            const ulonglong2* ur = reinterpret_cast<const ulonglong2*>(sWhh + j * H);
            const ulonglong2* uz = reinterpret_cast<const ulonglong2*>(sWhh + (j + H) * H);
            const ulonglong2* un = reinterpret_cast<const ulonglong2*>(sWhh + (j + 2 * H) * H);

            const float4 bj = *reinterpret_cast<const float4*>(sBias + 4 * j);

            // biases folded into accumulator init (lo lane)
            u64 ara = pk2(bj.x, 0.f), aza = pk2(bj.y, 0.f), ana = pk2(bj.z, 0.f);
            u64 bra = 0, bza = 0, bna = pk2(bj.w, 0.f);
            u64 arb = pk2(bj.x, 0.f), azb = pk2(bj.y, 0.f), anb = pk2(bj.z, 0.f);
            u64 brb = 0, bzb = 0, bnb = pk2(bj.w, 0.f);

            #pragma unroll
            for (int k = 0; k < F / 4; k++) {
                const u64 xaL = xa2[2 * k], xaH = xa2[2 * k + 1];
                const u64 xbL = xb2[2 * k], xbH = xb2[2 * k + 1];
                const u64 haL = ha2[2 * k], haH = ha2[2 * k + 1];
                const u64 hbL = hb2[2 * k], hbH = hb2[2 * k + 1];
                ulonglong2 w;
                w = wr[k];
                ara = fma2(w.x, xaL, ara); ara = fma2(w.y, xaH, ara);
                arb = fma2(w.x, xbL, arb); arb = fma2(w.y, xbH, arb);
                w = wz[k];
                aza = fma2(w.x, xaL, aza); aza = fma2(w.y, xaH, aza);
                azb = fma2(w.x, xbL, azb); azb = fma2(w.y, xbH, azb);
                w = wn[k];
                ana = fma2(w.x, xaL, ana); ana = fma2(w.y, xaH, ana);
                anb = fma2(w.x, xbL, anb); anb = fma2(w.y, xbH, anb);
                w = ur[k];
                bra = fma2(w.x, haL, bra); bra = fma2(w.y, haH, bra);
                brb = fma2(w.x, hbL, brb); brb = fma2(w.y, hbH, brb);
                w = uz[k];
                bza = fma2(w.x, haL, bza); bza = fma2(w.y, haH, bza);
                bzb = fma2(w.x, hbL, bzb); bzb = fma2(w.y, hbH, bzb);
                w = un[k];
                bna = fma2(w.x, haL, bna); bna = fma2(w.y, haH, bna);
                bnb = fma2(w.x, hbL, bnb); bnb = fma2(w.y, hbH, bnb);
            }

            // seq A
            {
                float r   = sigm_hw(hsum2(add2(ara, bra)));
                float z   = sigm_hw(hsum2(add2(aza, bza)));
                float nn  = tanh_hw(fmaf(r, hsum2(bna), hsum2(ana)));
                float hold = lane2(ha2[j >> 1], j & 1);
                hna[j] = fmaf(z, hold - nn, nn);
            }
            // seq B
            {
                float r   = sigm_hw(hsum2(add2(arb, brb)));
                float z   = sigm_hw(hsum2(add2(azb, bzb)));
                float nn  = tanh_hw(fmaf(r, hsum2(bnb), hsum2(anb)));
                float hold = lane2(hb2[j >> 1], j & 1);
                hnb[j] = fmaf(z, hold - nn, nn);
            }
        }

        #pragma unroll
        for (int i = 0; i < H / 2; i++) {
            ha2[i] = pk2(hna[2 * i], hna[2 * i + 1]);
            hb2[i] = pk2(hnb[2 * i], hnb[2 * i + 1]);
        }
    }

    // ---- output projection: out = h_final @ W (32x16), both sequences ----
    float acca[S], accb[S];
    #pragma unroll
    for (int s = 0; s < S; s++) { acca[s] = 0.f; accb[s] = 0.f; }
    #pragma unroll
    for (int k = 0; k < H; k++) {
        const float hka = hna[k], hkb = hnb[k];
        #pragma unroll
        for (int s = 0; s < S; s++) {
            acca[s] = fmaf(hka, sWo[k * S + s], acca[s]);
            accb[s] = fmaf(hkb, sWo[k * S + s], accb[s]);
        }
    }
    float4* opa = reinterpret_cast<float4*>(out + (size_t)n0 * S);
    float4* opb = reinterpret_cast<float4*>(out + (size_t)n1 * S);
    #pragma unroll
    for (int q = 0; q < 4; q++) {
        opa[q] = make_float4(acca[4 * q], acca[4 * q + 1], acca[4 * q + 2], acca[4 * q + 3]);
        opb[q] = make_float4(accb[4 * q], accb[4 * q + 1], accb[4 * q + 2], accb[4 * q + 3]);
    }
}

extern "C" void kernel_launch(void* const* d_in, const int* in_sizes, int n_in,
                              void* d_out, int out_size) {
    (void)in_sizes; (void)n_in; (void)out_size;
    const float* spatial = (const float*)d_in[0];
    const float* met     = (const float*)d_in[1];
    const float* ctx     = (const float*)d_in[2];
    const float* Wih     = (const float*)d_in[3];
    const float* Whh     = (const float*)d_in[4];
    const float* bih     = (const float*)d_in[5];
    const float* bhh     = (const float*)d_in[6];
    const float* Wo      = (const float*)d_in[7];
    float* out           = (float*)d_out;

    gru_fused4_kernel<<<HALF / 64, 64>>>(spatial, met, ctx, Wih, Whh, bih, bhh, Wo, out);
}

// round 6
// speedup vs baseline: 4.3999x; 3.1229x over previous
#include <cuda_runtime.h>
#include <cstdint>

// TemporalViewModel GRU, R6: warp-level tensor cores via baseline PTX
// mma.sync.m16n8k16 (bf16 -> f32), which compiles for compute_103 (tcgen05
// does not). 1 warp = 16 sequences; the whole 24-step recurrence is warp-local:
// C-fragment of h_new IS the A-fragment of the next step (m16n8k16 layout
// identity), so no shuffles/SMEM/h round trips and no block syncs in the loop.
// Precision: two-term bf16 split (hi + lo), 3-term products (h*h + l*h + h*l).
// Weight B-fragments precomputed in SMEM in fragment order (1 LDS.64 each).

namespace {
constexpr int T_STEPS = 24;
constexpr int NSEQ    = 65536;       // B*X*Y
constexpr int S = 16, Mf = 8, Cf = 8;
constexpr int H = 32;
}
typedef uint32_t u32;

// pack two fp32 -> bf16x2 word, elem0 in low half
__device__ __forceinline__ u32 pkbf(float e0, float e1) {
    u32 d; asm("cvt.rn.bf16x2.f32 %0, %1, %2;" : "=r"(d) : "f"(e1), "f"(e0));
    return d;
}
// two-term split: hi word (rounded bf16) + lo word (residual bf16)
__device__ __forceinline__ void split2(float x0, float x1, u32& hi, u32& lo) {
    hi = pkbf(x0, x1);
    float f0 = __uint_as_float(hi << 16);
    float f1 = __uint_as_float(hi & 0xffff0000u);
    lo = pkbf(x0 - f0, x1 - f1);
}
__device__ __forceinline__ float tanh_hw(float x) {
    float y; asm("tanh.approx.f32 %0, %1;" : "=f"(y) : "f"(x)); return y;
}
__device__ __forceinline__ float sigm_hw(float x) {
    return fmaf(0.5f, tanh_hw(0.5f * x), 0.5f);
}
__device__ __forceinline__ void mma16816(float* c, const u32* a, u32 b0, u32 b1) {
    asm volatile(
        "mma.sync.aligned.m16n8k16.row.col.f32.bf16.bf16.f32 "
        "{%0,%1,%2,%3}, {%4,%5,%6,%7}, {%8,%9}, {%0,%1,%2,%3};"
        : "+f"(c[0]), "+f"(c[1]), "+f"(c[2]), "+f"(c[3])
        : "r"(a[0]), "r"(a[1]), "r"(a[2]), "r"(a[3]), "r"(b0), "r"(b1));
}

__global__ void __launch_bounds__(128)
gru_mma_kernel(const float* __restrict__ spatial,
               const float* __restrict__ met,
               const float* __restrict__ ctx,
               const float* __restrict__ Wih,   // (96, 32) row-major
               const float* __restrict__ Whh,   // (96, 32)
               const float* __restrict__ bih,   // (96,)
               const float* __restrict__ bhh,   // (96,)
               const float* __restrict__ Wo,    // (32, 16)
               float* __restrict__ out)         // (N, 16)
{
    // B fragments in exact m16n8k16 fragment order: word index
    //   (kc*12 + nt)*64 + lane*2 + wi   (wi: 0 -> b0 (k=2t..), 1 -> b1 (k+8))
    __shared__ __align__(16) u32 sBXh[1536], sBXl[1536];   // Wih^T frags hi/lo
    __shared__ __align__(16) u32 sBHh[1536], sBHl[1536];   // Whh^T frags
    __shared__ __align__(16) u32 sBOh[256],  sBOl[256];    // Wo frags

    const int tid = threadIdx.x;

    for (int w = tid; w < 1536; w += 128) {
        int f = w >> 6, r = w & 63, ln = r >> 1, wi = r & 1;
        int kc = f / 12, nt = f % 12;
        int g = ln >> 2, t = ln & 3;
        int n = nt * 8 + g;
        int k = kc * 16 + 2 * t + wi * 8;
        u32 hi, lo;
        split2(Wih[n * 32 + k], Wih[n * 32 + k + 1], hi, lo);
        sBXh[w] = hi; sBXl[w] = lo;
        split2(Whh[n * 32 + k], Whh[n * 32 + k + 1], hi, lo);
        sBHh[w] = hi; sBHl[w] = lo;
    }
    for (int w = tid; w < 256; w += 128) {
        int f = w >> 6, r = w & 63, ln = r >> 1, wi = r & 1;
        int kc = f >> 1, nt = f & 1;
        int g = ln >> 2, t = ln & 3;
        int n = nt * 8 + g;
        int k = kc * 16 + 2 * t + wi * 8;
        u32 hi, lo;
        split2(Wo[k * 16 + n], Wo[(k + 1) * 16 + n], hi, lo);  // B[k][n] = Wo[k][n]
        sBOh[w] = hi; sBOl[w] = lo;
    }
    __syncthreads();

    const int lane = tid & 31;
    const int g  = lane >> 2;        // group id (row within fragment)
    const int tq = lane & 3;         // thread-in-group (col pair)
    const int lane2 = lane * 2;

    // per-lane gate biases at this lane's 8 columns per gate
    float bR[8], bZ[8], bNX[8], bNH[8];
    #pragma unroll
    for (int q = 0; q < 4; q++) {
        int j = 8 * q + 2 * tq;
        bR[2*q]   = bih[j]     + bhh[j];
        bR[2*q+1] = bih[j+1]   + bhh[j+1];
        bZ[2*q]   = bih[32+j]  + bhh[32+j];
        bZ[2*q+1] = bih[32+j+1]+ bhh[32+j+1];
        bNX[2*q]  = bih[64+j];    bNX[2*q+1] = bih[64+j+1];
        bNH[2*q]  = bhh[64+j];    bNH[2*q+1] = bhh[64+j+1];
    }

    // this warp's 16 sequences
    const int warp_g = blockIdx.x * 4 + (tid >> 5);
    const int seq0 = warp_g * 16 + g;
    const int seq1 = seq0 + 8;

    const float* sp0 = spatial + (size_t)seq0 * S  + 2 * tq;
    const float* sp1 = spatial + (size_t)seq1 * S  + 2 * tq;
    const float* mp0 = met     + (size_t)seq0 * Mf + 2 * tq;
    const float* mp1 = met     + (size_t)seq1 * Mf + 2 * tq;
    const float* cp0 = ctx     + (size_t)seq0 * Cf + 2 * tq;
    const float* cp1 = ctx     + (size_t)seq1 * Cf + 2 * tq;

    // hidden state in C-fragment layout: hC[tile][c0..c3], tiles cover cols 0..31
    float hC[4][4];
    u32 Ahh[2][4] = {{0,0,0,0},{0,0,0,0}};   // h A-frags hi (bf16(0) == 0)
    u32 Ahl[2][4] = {{0,0,0,0},{0,0,0,0}};   // lo
    #pragma unroll
    for (int q = 0; q < 4; q++)
        #pragma unroll
        for (int i = 0; i < 4; i++) hC[q][i] = 0.f;

    #pragma unroll 1
    for (int t = 0; t < T_STEPS; t++) {
        // ---- x A-fragments straight from GMEM ----
        u32 Axh[2][4], Axl[2][4];
        {
            float2 v;
            v = *(const float2*)(sp0);     split2(v.x, v.y, Axh[0][0], Axl[0][0]);
            v = *(const float2*)(sp1);     split2(v.x, v.y, Axh[0][1], Axl[0][1]);
            v = *(const float2*)(sp0 + 8); split2(v.x, v.y, Axh[0][2], Axl[0][2]);
            v = *(const float2*)(sp1 + 8); split2(v.x, v.y, Axh[0][3], Axl[0][3]);
            v = *(const float2*)(mp0);     split2(v.x, v.y, Axh[1][0], Axl[1][0]);
            v = *(const float2*)(mp1);     split2(v.x, v.y, Axh[1][1], Axl[1][1]);
            v = *(const float2*)(cp0);     split2(v.x, v.y, Axh[1][2], Axl[1][2]);
            v = *(const float2*)(cp1);     split2(v.x, v.y, Axh[1][3], Axl[1][3]);
            sp0 += (size_t)NSEQ * S;  sp1 += (size_t)NSEQ * S;
            mp0 += (size_t)NSEQ * Mf; mp1 += (size_t)NSEQ * Mf;
            cp0 += (size_t)NSEQ * Cf; cp1 += (size_t)NSEQ * Cf;
        }

        // ---- init C from biases: tiles 0-3 r, 4-7 z, 8-11 n_x, 12-15 n_h ----
        float acc[16][4];
        #pragma unroll
        for (int q = 0; q < 4; q++) {
            acc[q][0]    = bR[2*q];  acc[q][1]    = bR[2*q+1];
            acc[q][2]    = bR[2*q];  acc[q][3]    = bR[2*q+1];
            acc[4+q][0]  = bZ[2*q];  acc[4+q][1]  = bZ[2*q+1];
            acc[4+q][2]  = bZ[2*q];  acc[4+q][3]  = bZ[2*q+1];
            acc[8+q][0]  = bNX[2*q]; acc[8+q][1]  = bNX[2*q+1];
            acc[8+q][2]  = bNX[2*q]; acc[8+q][3]  = bNX[2*q+1];
            acc[12+q][0] = bNH[2*q]; acc[12+q][1] = bNH[2*q+1];
            acc[12+q][2] = bNH[2*q]; acc[12+q][3] = bNH[2*q+1];
        }

        // ---- x @ Wih^T : n-tiles 0..11 -> C tiles 0..11 ----
        #pragma unroll
        for (int kc = 0; kc < 2; kc++)
            #pragma unroll
            for (int nt = 0; nt < 12; nt++) {
                int fo = (kc * 12 + nt) * 64 + lane2;
                uint2 bh = *(const uint2*)&sBXh[fo];
                uint2 bl = *(const uint2*)&sBXl[fo];
                float* cd = acc[nt];
                mma16816(cd, Axh[kc], bh.x, bh.y);
                mma16816(cd, Axl[kc], bh.x, bh.y);
                mma16816(cd, Axh[kc], bl.x, bl.y);
            }

        // ---- h @ Whh^T : rz tiles 0..7 shared, n_h -> tiles 12..15 ----
        #pragma unroll
        for (int kc = 0; kc < 2; kc++)
            #pragma unroll
            for (int nt = 0; nt < 12; nt++) {
                int fo = (kc * 12 + nt) * 64 + lane2;
                uint2 bh = *(const uint2*)&sBHh[fo];
                uint2 bl = *(const uint2*)&sBHl[fo];
                float* cd = acc[nt < 8 ? nt : nt + 4];
                mma16816(cd, Ahh[kc], bh.x, bh.y);
                mma16816(cd, Ahl[kc], bh.x, bh.y);
                mma16816(cd, Ahh[kc], bl.x, bl.y);
            }

        // ---- epilogue: GRU pointwise, fully lane-local ----
        #pragma unroll
        for (int q = 0; q < 4; q++) {
            #pragma unroll
            for (int i = 0; i < 4; i++) {
                float r  = sigm_hw(acc[q][i]);
                float z  = sigm_hw(acc[4 + q][i]);
                float nn = tanh_hw(fmaf(r, acc[12 + q][i], acc[8 + q][i]));
                hC[q][i] = fmaf(z, hC[q][i] - nn, nn);
            }
        }

        // ---- h C-fragments -> A-fragments for next step (layout identity) ----
        split2(hC[0][0], hC[0][1], Ahh[0][0], Ahl[0][0]);
        split2(hC[0][2], hC[0][3], Ahh[0][1], Ahl[0][1]);
        split2(hC[1][0], hC[1][1], Ahh[0][2], Ahl[0][2]);
        split2(hC[1][2], hC[1][3], Ahh[0][3], Ahl[0][3]);
        split2(hC[2][0], hC[2][1], Ahh[1][0], Ahl[1][0]);
        split2(hC[2][2], hC[2][3], Ahh[1][1], Ahl[1][1]);
        split2(hC[3][0], hC[3][1], Ahh[1][2], Ahl[1][2]);
        split2(hC[3][2], hC[3][3], Ahh[1][3], Ahl[1][3]);
    }

    // ---- output projection: out[16 x 16] = h @ Wo via 12 MMAs ----
    float co[2][4];
    #pragma unroll
    for (int nt = 0; nt < 2; nt++)
        #pragma unroll
        for (int i = 0; i < 4; i++) co[nt][i] = 0.f;
    #pragma unroll
    for (int kc = 0; kc < 2; kc++)
        #pragma unroll
        for (int nt = 0; nt < 2; nt++) {
            int fo = (kc * 2 + nt) * 64 + lane2;
            uint2 bh = *(const uint2*)&sBOh[fo];
            uint2 bl = *(const uint2*)&sBOl[fo];
            mma16816(co[nt], Ahh[kc], bh.x, bh.y);
            mma16816(co[nt], Ahl[kc], bh.x, bh.y);
            mma16816(co[nt], Ahh[kc], bl.x, bl.y);
        }
    #pragma unroll
    for (int nt = 0; nt < 2; nt++) {
        *(float2*)(out + (size_t)seq0 * 16 + nt * 8 + 2 * tq) = make_float2(co[nt][0], co[nt][1]);
        *(float2*)(out + (size_t)seq1 * 16 + nt * 8 + 2 * tq) = make_float2(co[nt][2], co[nt][3]);
    }
}

extern "C" void kernel_launch(void* const* d_in, const int* in_sizes, int n_in,
                              void* d_out, int out_size) {
    (void)in_sizes; (void)n_in; (void)out_size;
    const float* spatial = (const float*)d_in[0];
    const float* met     = (const float*)d_in[1];
    const float* ctx     = (const float*)d_in[2];
    const float* Wih     = (const float*)d_in[3];
    const float* Whh     = (const float*)d_in[4];
    const float* bih     = (const float*)d_in[5];
    const float* bhh     = (const float*)d_in[6];
    const float* Wo      = (const float*)d_in[7];
    float* out           = (float*)d_out;

    // 4096 warps (16 seqs each) / 4 warps per block = 1024 blocks
    gru_mma_kernel<<<NSEQ / 64, 128>>>(spatial, met, ctx, Wih, Whh, bih, bhh, Wo, out);
}

// round 7
// speedup vs baseline: 4.9875x; 1.1336x over previous
#include <cuda_runtime.h>
#include <cstdint>

// TemporalViewModel GRU, R7: warp-level mma.sync.m16n8k16 bf16 path (R6 base).
// Change vs R6: the 32 per-lane bias registers move to SMEM and are applied in
// the epilogue; __launch_bounds__(128,3) caps regs at 170 so 3 CTAs fit per SM
// (occupancy 2 -> 3 warps/SMSP), lifting tensor-pipe utilization.

namespace {
constexpr int T_STEPS = 24;
constexpr int NSEQ    = 65536;       // B*X*Y
constexpr int S = 16, Mf = 8, Cf = 8;
}
typedef uint32_t u32;

__device__ __forceinline__ u32 pkbf(float e0, float e1) {
    u32 d; asm("cvt.rn.bf16x2.f32 %0, %1, %2;" : "=r"(d) : "f"(e1), "f"(e0));
    return d;
}
__device__ __forceinline__ void split2(float x0, float x1, u32& hi, u32& lo) {
    hi = pkbf(x0, x1);
    float f0 = __uint_as_float(hi << 16);
    float f1 = __uint_as_float(hi & 0xffff0000u);
    lo = pkbf(x0 - f0, x1 - f1);
}
__device__ __forceinline__ float tanh_hw(float x) {
    float y; asm("tanh.approx.f32 %0, %1;" : "=f"(y) : "f"(x)); return y;
}
__device__ __forceinline__ float sigm_hw(float x) {
    return fmaf(0.5f, tanh_hw(0.5f * x), 0.5f);
}
__device__ __forceinline__ void mma16816(float* c, const u32* a, u32 b0, u32 b1) {
    asm volatile(
        "mma.sync.aligned.m16n8k16.row.col.f32.bf16.bf16.f32 "
        "{%0,%1,%2,%3}, {%4,%5,%6,%7}, {%8,%9}, {%0,%1,%2,%3};"
        : "+f"(c[0]), "+f"(c[1]), "+f"(c[2]), "+f"(c[3])
        : "r"(a[0]), "r"(a[1]), "r"(a[2]), "r"(a[3]), "r"(b0), "r"(b1));
}

__global__ void __launch_bounds__(128, 3)
gru_mma_kernel(const float* __restrict__ spatial,
               const float* __restrict__ met,
               const float* __restrict__ ctx,
               const float* __restrict__ Wih,   // (96, 32) row-major
               const float* __restrict__ Whh,   // (96, 32)
               const float* __restrict__ bih,   // (96,)
               const float* __restrict__ bhh,   // (96,)
               const float* __restrict__ Wo,    // (32, 16)
               float* __restrict__ out)         // (N, 16)
{
    // B fragments in m16n8k16 fragment order: word idx (kc*12+nt)*64 + lane*2 + wi
    __shared__ __align__(16) u32 sBXh[1536], sBXl[1536];   // Wih^T frags hi/lo
    __shared__ __align__(16) u32 sBHh[1536], sBHl[1536];   // Whh^T frags
    __shared__ __align__(16) u32 sBOh[256],  sBOl[256];    // Wo frags
    __shared__ __align__(8)  float sBr[32], sBz[32], sBnx[32], sBnh[32];

    const int tid = threadIdx.x;

    for (int w = tid; w < 1536; w += 128) {
        int f = w >> 6, r = w & 63, ln = r >> 1, wi = r & 1;
        int kc = f / 12, nt = f % 12;
        int g = ln >> 2, t = ln & 3;
        int n = nt * 8 + g;
        int k = kc * 16 + 2 * t + wi * 8;
        u32 hi, lo;
        split2(Wih[n * 32 + k], Wih[n * 32 + k + 1], hi, lo);
        sBXh[w] = hi; sBXl[w] = lo;
        split2(Whh[n * 32 + k], Whh[n * 32 + k + 1], hi, lo);
        sBHh[w] = hi; sBHl[w] = lo;
    }
    for (int w = tid; w < 256; w += 128) {
        int f = w >> 6, r = w & 63, ln = r >> 1, wi = r & 1;
        int kc = f >> 1, nt = f & 1;
        int g = ln >> 2, t = ln & 3;
        int n = nt * 8 + g;
        int k = kc * 16 + 2 * t + wi * 8;
        u32 hi, lo;
        split2(Wo[k * 16 + n], Wo[(k + 1) * 16 + n], hi, lo);
        sBOh[w] = hi; sBOl[w] = lo;
    }
    if (tid < 32) {
        sBr[tid]  = bih[tid]      + bhh[tid];
        sBz[tid]  = bih[32 + tid] + bhh[32 + tid];
        sBnx[tid] = bih[64 + tid];
        sBnh[tid] = bhh[64 + tid];
    }
    __syncthreads();

    const int lane = tid & 31;
    const int g  = lane >> 2;
    const int tq = lane & 3;
    const int lane2 = lane * 2;

    const int warp_g = blockIdx.x * 4 + (tid >> 5);
    const int seq0 = warp_g * 16 + g;
    const int seq1 = seq0 + 8;

    const float* sp0 = spatial + (size_t)seq0 * S  + 2 * tq;
    const float* sp1 = spatial + (size_t)seq1 * S  + 2 * tq;
    const float* mp0 = met     + (size_t)seq0 * Mf + 2 * tq;
    const float* mp1 = met     + (size_t)seq1 * Mf + 2 * tq;
    const float* cp0 = ctx     + (size_t)seq0 * Cf + 2 * tq;
    const float* cp1 = ctx     + (size_t)seq1 * Cf + 2 * tq;

    float hC[4][4];
    u32 Ahh[2][4] = {{0,0,0,0},{0,0,0,0}};
    u32 Ahl[2][4] = {{0,0,0,0},{0,0,0,0}};
    #pragma unroll
    for (int q = 0; q < 4; q++)
        #pragma unroll
        for (int i = 0; i < 4; i++) hC[q][i] = 0.f;

    #pragma unroll 1
    for (int t = 0; t < T_STEPS; t++) {
        // ---- x A-fragments straight from GMEM ----
        u32 Axh[2][4], Axl[2][4];
        {
            float2 v;
            v = *(const float2*)(sp0);     split2(v.x, v.y, Axh[0][0], Axl[0][0]);
            v = *(const float2*)(sp1);     split2(v.x, v.y, Axh[0][1], Axl[0][1]);
            v = *(const float2*)(sp0 + 8); split2(v.x, v.y, Axh[0][2], Axl[0][2]);
            v = *(const float2*)(sp1 + 8); split2(v.x, v.y, Axh[0][3], Axl[0][3]);
            v = *(const float2*)(mp0);     split2(v.x, v.y, Axh[1][0], Axl[1][0]);
            v = *(const float2*)(mp1);     split2(v.x, v.y, Axh[1][1], Axl[1][1]);
            v = *(const float2*)(cp0);     split2(v.x, v.y, Axh[1][2], Axl[1][2]);
            v = *(const float2*)(cp1);     split2(v.x, v.y, Axh[1][3], Axl[1][3]);
            sp0 += (size_t)NSEQ * S;  sp1 += (size_t)NSEQ * S;
            mp0 += (size_t)NSEQ * Mf; mp1 += (size_t)NSEQ * Mf;
            cp0 += (size_t)NSEQ * Cf; cp1 += (size_t)NSEQ * Cf;
        }

        // ---- C tiles: 0-3 r, 4-7 z, 8-11 n_x, 12-15 n_h (zero init) ----
        float acc[16][4];
        #pragma unroll
        for (int q = 0; q < 16; q++)
            #pragma unroll
            for (int i = 0; i < 4; i++) acc[q][i] = 0.f;

        // ---- x @ Wih^T ----
        #pragma unroll
        for (int kc = 0; kc < 2; kc++)
            #pragma unroll
            for (int nt = 0; nt < 12; nt++) {
                int fo = (kc * 12 + nt) * 64 + lane2;
                uint2 bh = *(const uint2*)&sBXh[fo];
                uint2 bl = *(const uint2*)&sBXl[fo];
                float* cd = acc[nt];
                mma16816(cd, Axh[kc], bh.x, bh.y);
                mma16816(cd, Axl[kc], bh.x, bh.y);
                mma16816(cd, Axh[kc], bl.x, bl.y);
            }

        // ---- h @ Whh^T (rz tiles shared, n_h -> 12..15) ----
        #pragma unroll
        for (int kc = 0; kc < 2; kc++)
            #pragma unroll
            for (int nt = 0; nt < 12; nt++) {
                int fo = (kc * 12 + nt) * 64 + lane2;
                uint2 bh = *(const uint2*)&sBHh[fo];
                uint2 bl = *(const uint2*)&sBHl[fo];
                float* cd = acc[nt < 8 ? nt : nt + 4];
                mma16816(cd, Ahh[kc], bh.x, bh.y);
                mma16816(cd, Ahl[kc], bh.x, bh.y);
                mma16816(cd, Ahh[kc], bl.x, bl.y);
            }

        // ---- epilogue: biases from SMEM + GRU pointwise ----
        #pragma unroll
        for (int q = 0; q < 4; q++) {
            const int cp2 = 4 * q + tq;   // float2 index of this lane's col pair
            const float2 brv  = ((const float2*)sBr)[cp2];
            const float2 bzv  = ((const float2*)sBz)[cp2];
            const float2 bnxv = ((const float2*)sBnx)[cp2];
            const float2 bnhv = ((const float2*)sBnh)[cp2];
            #pragma unroll
            for (int i = 0; i < 4; i++) {
                const float br_  = (i & 1) ? brv.y  : brv.x;
                const float bz_  = (i & 1) ? bzv.y  : bzv.x;
                const float bnx_ = (i & 1) ? bnxv.y : bnxv.x;
                const float bnh_ = (i & 1) ? bnhv.y : bnhv.x;
                float r  = sigm_hw(acc[q][i] + br_);
                float z  = sigm_hw(acc[4 + q][i] + bz_);
                float nn = tanh_hw(acc[8 + q][i] + bnx_ + r * (acc[12 + q][i] + bnh_));
                hC[q][i] = fmaf(z, hC[q][i] - nn, nn);
            }
        }

        // ---- h C-fragments -> next step's A-fragments (layout identity) ----
        split2(hC[0][0], hC[0][1], Ahh[0][0], Ahl[0][0]);
        split2(hC[0][2], hC[0][3], Ahh[0][1], Ahl[0][1]);
        split2(hC[1][0], hC[1][1], Ahh[0][2], Ahl[0][2]);
        split2(hC[1][2], hC[1][3], Ahh[0][3], Ahl[0][3]);
        split2(hC[2][0], hC[2][1], Ahh[1][0], Ahl[1][0]);
        split2(hC[2][2], hC[2][3], Ahh[1][1], Ahl[1][1]);
        split2(hC[3][0], hC[3][1], Ahh[1][2], Ahl[1][2]);
        split2(hC[3][2], hC[3][3], Ahh[1][3], Ahl[1][3]);
    }

    // ---- output projection: out[16 x 16] = h @ Wo via 12 MMAs ----
    float co[2][4];
    #pragma unroll
    for (int nt = 0; nt < 2; nt++)
        #pragma unroll
        for (int i = 0; i < 4; i++) co[nt][i] = 0.f;
    #pragma unroll
    for (int kc = 0; kc < 2; kc++)
        #pragma unroll
        for (int nt = 0; nt < 2; nt++) {
            int fo = (kc * 2 + nt) * 64 + lane2;
            uint2 bh = *(const uint2*)&sBOh[fo];
            uint2 bl = *(const uint2*)&sBOl[fo];
            mma16816(co[nt], Ahh[kc], bh.x, bh.y);
            mma16816(co[nt], Ahl[kc], bh.x, bh.y);
            mma16816(co[nt], Ahh[kc], bl.x, bl.y);
        }
    #pragma unroll
    for (int nt = 0; nt < 2; nt++) {
        *(float2*)(out + (size_t)seq0 * 16 + nt * 8 + 2 * tq) = make_float2(co[nt][0], co[nt][1]);
        *(float2*)(out + (size_t)seq1 * 16 + nt * 8 + 2 * tq) = make_float2(co[nt][2], co[nt][3]);
    }
}

extern "C" void kernel_launch(void* const* d_in, const int* in_sizes, int n_in,
                              void* d_out, int out_size) {
    (void)in_sizes; (void)n_in; (void)out_size;
    const float* spatial = (const float*)d_in[0];
    const float* met     = (const float*)d_in[1];
    const float* ctx     = (const float*)d_in[2];
    const float* Wih     = (const float*)d_in[3];
    const float* Whh     = (const float*)d_in[4];
    const float* bih     = (const float*)d_in[5];
    const float* bhh     = (const float*)d_in[6];
    const float* Wo      = (const float*)d_in[7];
    float* out           = (float*)d_out;

    gru_mma_kernel<<<NSEQ / 64, 128>>>(spatial, met, ctx, Wih, Whh, bih, bhh, Wo, out);
}

// round 10
// speedup vs baseline: 5.3769x; 1.0781x over previous
#include <cuda_runtime.h>
#include <cstdint>

// TemporalViewModel GRU, R8: warp-level mma.sync.m16n8k16 bf16 path.
// Change vs R7: gate computation split into 4 register-phases
// (r -> n_h -> n_x-into-g -> z) so peak accumulator live drops 64 -> 32 regs;
// __launch_bounds__(128,4) targets 4 CTAs/SM (4 warps/SMSP) to lift the
// tensor pipe past the 59% of R7. MMA count unchanged (144/step, 3-term
// bf16 hi/lo split for ~fp32 precision).

namespace {
constexpr int T_STEPS = 24;
constexpr int NSEQ    = 65536;       // B*X*Y
constexpr int S = 16, Mf = 8, Cf = 8;
}
typedef uint32_t u32;

__device__ __forceinline__ u32 pkbf(float e0, float e1) {
    u32 d; asm("cvt.rn.bf16x2.f32 %0, %1, %2;" : "=r"(d) : "f"(e1), "f"(e0));
    return d;
}
__device__ __forceinline__ void split2(float x0, float x1, u32& hi, u32& lo) {
    hi = pkbf(x0, x1);
    float f0 = __uint_as_float(hi << 16);
    float f1 = __uint_as_float(hi & 0xffff0000u);
    lo = pkbf(x0 - f0, x1 - f1);
}
__device__ __forceinline__ float tanh_hw(float x) {
    float y; asm("tanh.approx.f32 %0, %1;" : "=f"(y) : "f"(x)); return y;
}
__device__ __forceinline__ float sigm_hw(float x) {
    return fmaf(0.5f, tanh_hw(0.5f * x), 0.5f);
}
__device__ __forceinline__ void mma16816(float* c, const u32* a, u32 b0, u32 b1) {
    asm volatile(
        "mma.sync.aligned.m16n8k16.row.col.f32.bf16.bf16.f32 "
        "{%0,%1,%2,%3}, {%4,%5,%6,%7}, {%8,%9}, {%0,%1,%2,%3};"
        : "+f"(c[0]), "+f"(c[1]), "+f"(c[2]), "+f"(c[3])
        : "r"(a[0]), "r"(a[1]), "r"(a[2]), "r"(a[3]), "r"(b0), "r"(b1));
}

__global__ void __launch_bounds__(128, 4)
gru_mma_kernel(const float* __restrict__ spatial,
               const float* __restrict__ met,
               const float* __restrict__ ctx,
               const float* __restrict__ Wih,   // (96, 32) row-major
               const float* __restrict__ Whh,   // (96, 32)
               const float* __restrict__ bih,   // (96,)
               const float* __restrict__ bhh,   // (96,)
               const float* __restrict__ Wo,    // (32, 16)
               float* __restrict__ out)         // (N, 16)
{
    // B fragments in m16n8k16 fragment order: word idx (kc*12+nt)*64 + lane*2 + wi
    // nt 0..3 = r tiles, 4..7 = z tiles, 8..11 = n tiles.
    __shared__ __align__(16) u32 sBXh[1536], sBXl[1536];   // Wih^T frags hi/lo
    __shared__ __align__(16) u32 sBHh[1536], sBHl[1536];   // Whh^T frags
    __shared__ __align__(16) u32 sBOh[256],  sBOl[256];    // Wo frags
    __shared__ __align__(8)  float sBr[32], sBz[32], sBnx[32], sBnh[32];

    const int tid = threadIdx.x;

    for (int w = tid; w < 1536; w += 128) {
        int f = w >> 6, r = w & 63, ln = r >> 1, wi = r & 1;
        int kc = f / 12, nt = f % 12;
        int g = ln >> 2, t = ln & 3;
        int n = nt * 8 + g;
        int k = kc * 16 + 2 * t + wi * 8;
        u32 hi, lo;
        split2(Wih[n * 32 + k], Wih[n * 32 + k + 1], hi, lo);
        sBXh[w] = hi; sBXl[w] = lo;
        split2(Whh[n * 32 + k], Whh[n * 32 + k + 1], hi, lo);
        sBHh[w] = hi; sBHl[w] = lo;
    }
    for (int w = tid; w < 256; w += 128) {
        int f = w >> 6, r = w & 63, ln = r >> 1, wi = r & 1;
        int kc = f >> 1, nt = f & 1;
        int g = ln >> 2, t = ln & 3;
        int n = nt * 8 + g;
        int k = kc * 16 + 2 * t + wi * 8;
        u32 hi, lo;
        split2(Wo[k * 16 + n], Wo[(k + 1) * 16 + n], hi, lo);
        sBOh[w] = hi; sBOl[w] = lo;
    }
    if (tid < 32) {
        sBr[tid]  = bih[tid]      + bhh[tid];
        sBz[tid]  = bih[32 + tid] + bhh[32 + tid];
        sBnx[tid] = bih[64 + tid];
        sBnh[tid] = bhh[64 + tid];
    }
    __syncthreads();

    const int lane = tid & 31;
    const int g  = lane >> 2;
    const int tq = lane & 3;
    const int lane2 = lane * 2;

    const int warp_g = blockIdx.x * 4 + (tid >> 5);
    const int seq0 = warp_g * 16 + g;
    const int seq1 = seq0 + 8;

    const float* sp0 = spatial + (size_t)seq0 * S  + 2 * tq;
    const float* sp1 = spatial + (size_t)seq1 * S  + 2 * tq;
    const float* mp0 = met     + (size_t)seq0 * Mf + 2 * tq;
    const float* mp1 = met     + (size_t)seq1 * Mf + 2 * tq;
    const float* cp0 = ctx     + (size_t)seq0 * Cf + 2 * tq;
    const float* cp1 = ctx     + (size_t)seq1 * Cf + 2 * tq;

    float hC[4][4];
    u32 Ahh[2][4] = {{0,0,0,0},{0,0,0,0}};
    u32 Ahl[2][4] = {{0,0,0,0},{0,0,0,0}};
    #pragma unroll
    for (int q = 0; q < 4; q++)
        #pragma unroll
        for (int i = 0; i < 4; i++) hC[q][i] = 0.f;

    #pragma unroll 1
    for (int t = 0; t < T_STEPS; t++) {
        // ---- x A-fragments straight from GMEM ----
        u32 Axh[2][4], Axl[2][4];
        {
            float2 v;
            v = *(const float2*)(sp0);     split2(v.x, v.y, Axh[0][0], Axl[0][0]);
            v = *(const float2*)(sp1);     split2(v.x, v.y, Axh[0][1], Axl[0][1]);
            v = *(const float2*)(sp0 + 8); split2(v.x, v.y, Axh[0][2], Axl[0][2]);
            v = *(const float2*)(sp1 + 8); split2(v.x, v.y, Axh[0][3], Axl[0][3]);
            v = *(const float2*)(mp0);     split2(v.x, v.y, Axh[1][0], Axl[1][0]);
            v = *(const float2*)(mp1);     split2(v.x, v.y, Axh[1][1], Axl[1][1]);
            v = *(const float2*)(cp0);     split2(v.x, v.y, Axh[1][2], Axl[1][2]);
            v = *(const float2*)(cp1);     split2(v.x, v.y, Axh[1][3], Axl[1][3]);
            sp0 += (size_t)NSEQ * S;  sp1 += (size_t)NSEQ * S;
            mp0 += (size_t)NSEQ * Mf; mp1 += (size_t)NSEQ * Mf;
            cp0 += (size_t)NSEQ * Cf; cp1 += (size_t)NSEQ * Cf;
        }

        float nn[4][4];   // becomes g then n; peak acc live = one phase (16) + nn (16)

        // ======== phase 1: r tiles (nt 0..3) ========
        {
            float acc[4][4];
            #pragma unroll
            for (int q = 0; q < 4; q++)
                #pragma unroll
                for (int i = 0; i < 4; i++) acc[q][i] = 0.f;
            #pragma unroll
            for (int kc = 0; kc < 2; kc++)
                #pragma unroll
                for (int nt = 0; nt < 4; nt++) {
                    int fo = (kc * 12 + nt) * 64 + lane2;
                    uint2 bh = *(const uint2*)&sBXh[fo];
                    uint2 bl = *(const uint2*)&sBXl[fo];
                    mma16816(acc[nt], Axh[kc], bh.x, bh.y);
                    mma16816(acc[nt], Axl[kc], bh.x, bh.y);
                    mma16816(acc[nt], Axh[kc], bl.x, bl.y);
                    uint2 ch = *(const uint2*)&sBHh[fo];
                    uint2 cl = *(const uint2*)&sBHl[fo];
                    mma16816(acc[nt], Ahh[kc], ch.x, ch.y);
                    mma16816(acc[nt], Ahl[kc], ch.x, ch.y);
                    mma16816(acc[nt], Ahh[kc], cl.x, cl.y);
                }
            // r into nn temporarily
            #pragma unroll
            for (int q = 0; q < 4; q++) {
                const float2 brv = ((const float2*)sBr)[4 * q + tq];
                #pragma unroll
                for (int i = 0; i < 4; i++)
                    nn[q][i] = sigm_hw(acc[q][i] + ((i & 1) ? brv.y : brv.x));
            }
        }

        // ======== phase 2: n_h tiles (nt 8..11), consume r ========
        {
            float acc[4][4];
            #pragma unroll
            for (int q = 0; q < 4; q++)
                #pragma unroll
                for (int i = 0; i < 4; i++) acc[q][i] = 0.f;
            #pragma unroll
            for (int kc = 0; kc < 2; kc++)
                #pragma unroll
                for (int nt = 0; nt < 4; nt++) {
                    int fo = (kc * 12 + 8 + nt) * 64 + lane2;
                    uint2 ch = *(const uint2*)&sBHh[fo];
                    uint2 cl = *(const uint2*)&sBHl[fo];
                    mma16816(acc[nt], Ahh[kc], ch.x, ch.y);
                    mma16816(acc[nt], Ahl[kc], ch.x, ch.y);
                    mma16816(acc[nt], Ahh[kc], cl.x, cl.y);
                }
            // g = bnx + r * (acc + bnh)   (r was in nn; overwrite in place)
            #pragma unroll
            for (int q = 0; q < 4; q++) {
                const float2 bnxv = ((const float2*)sBnx)[4 * q + tq];
                const float2 bnhv = ((const float2*)sBnh)[4 * q + tq];
                #pragma unroll
                for (int i = 0; i < 4; i++) {
                    const float bx = (i & 1) ? bnxv.y : bnxv.x;
                    const float bb = (i & 1) ? bnhv.y : bnhv.x;
                    nn[q][i] = fmaf(nn[q][i], acc[q][i] + bb, bx);
                }
            }
        }

        // ======== phase 3: n_x tiles accumulate directly into g ========
        #pragma unroll
        for (int kc = 0; kc < 2; kc++)
            #pragma unroll
            for (int nt = 0; nt < 4; nt++) {
                int fo = (kc * 12 + 8 + nt) * 64 + lane2;
                uint2 bh = *(const uint2*)&sBXh[fo];
                uint2 bl = *(const uint2*)&sBXl[fo];
                mma16816(nn[nt], Axh[kc], bh.x, bh.y);
                mma16816(nn[nt], Axl[kc], bh.x, bh.y);
                mma16816(nn[nt], Axh[kc], bl.x, bl.y);
            }
        #pragma unroll
        for (int q = 0; q < 4; q++)
            #pragma unroll
            for (int i = 0; i < 4; i++) nn[q][i] = tanh_hw(nn[q][i]);

        // ======== phase 4: z tiles (nt 4..7) + combine ========
        {
            float acc[4][4];
            #pragma unroll
            for (int q = 0; q < 4; q++)
                #pragma unroll
                for (int i = 0; i < 4; i++) acc[q][i] = 0.f;
            #pragma unroll
            for (int kc = 0; kc < 2; kc++)
                #pragma unroll
                for (int nt = 0; nt < 4; nt++) {
                    int fo = (kc * 12 + 4 + nt) * 64 + lane2;
                    uint2 bh = *(const uint2*)&sBXh[fo];
                    uint2 bl = *(const uint2*)&sBXl[fo];
                    mma16816(acc[nt], Axh[kc], bh.x, bh.y);
                    mma16816(acc[nt], Axl[kc], bh.x, bh.y);
                    mma16816(acc[nt], Axh[kc], bl.x, bl.y);
                    uint2 ch = *(const uint2*)&sBHh[fo];
                    uint2 cl = *(const uint2*)&sBHl[fo];
                    mma16816(acc[nt], Ahh[kc], ch.x, ch.y);
                    mma16816(acc[nt], Ahl[kc], ch.x, ch.y);
                    mma16816(acc[nt], Ahh[kc], cl.x, cl.y);
                }
            #pragma unroll
            for (int q = 0; q < 4; q++) {
                const float2 bzv = ((const float2*)sBz)[4 * q + tq];
                #pragma unroll
                for (int i = 0; i < 4; i++) {
                    float z = sigm_hw(acc[q][i] + ((i & 1) ? bzv.y : bzv.x));
                    hC[q][i] = fmaf(z, hC[q][i] - nn[q][i], nn[q][i]);
                }
            }
        }

        // ---- h C-fragments -> next step's A-fragments (layout identity) ----
        split2(hC[0][0], hC[0][1], Ahh[0][0], Ahl[0][0]);
        split2(hC[0][2], hC[0][3], Ahh[0][1], Ahl[0][1]);
        split2(hC[1][0], hC[1][1], Ahh[0][2], Ahl[0][2]);
        split2(hC[1][2], hC[1][3], Ahh[0][3], Ahl[0][3]);
        split2(hC[2][0], hC[2][1], Ahh[1][0], Ahl[1][0]);
        split2(hC[2][2], hC[2][3], Ahh[1][1], Ahl[1][1]);
        split2(hC[3][0], hC[3][1], Ahh[1][2], Ahl[1][2]);
        split2(hC[3][2], hC[3][3], Ahh[1][3], Ahl[1][3]);
    }

    // ---- output projection: out[16 x 16] = h @ Wo via 12 MMAs ----
    float co[2][4];
    #pragma unroll
    for (int nt = 0; nt < 2; nt++)
        #pragma unroll
        for (int i = 0; i < 4; i++) co[nt][i] = 0.f;
    #pragma unroll
    for (int kc = 0; kc < 2; kc++)
        #pragma unroll
        for (int nt = 0; nt < 2; nt++) {
            int fo = (kc * 2 + nt) * 64 + lane2;
            uint2 bh = *(const uint2*)&sBOh[fo];
            uint2 bl = *(const uint2*)&sBOl[fo];
            mma16816(co[nt], Ahh[kc], bh.x, bh.y);
            mma16816(co[nt], Ahl[kc], bh.x, bh.y);
            mma16816(co[nt], Ahh[kc], bl.x, bl.y);
        }
    #pragma unroll
    for (int nt = 0; nt < 2; nt++) {
        *(float2*)(out + (size_t)seq0 * 16 + nt * 8 + 2 * tq) = make_float2(co[nt][0], co[nt][1]);
        *(float2*)(out + (size_t)seq1 * 16 + nt * 8 + 2 * tq) = make_float2(co[nt][2], co[nt][3]);
    }
}

extern "C" void kernel_launch(void* const* d_in, const int* in_sizes, int n_in,
                              void* d_out, int out_size) {
    (void)in_sizes; (void)n_in; (void)out_size;
    const float* spatial = (const float*)d_in[0];
    const float* met     = (const float*)d_in[1];
    const float* ctx     = (const float*)d_in[2];
    const float* Wih     = (const float*)d_in[3];
    const float* Whh     = (const float*)d_in[4];
    const float* bih     = (const float*)d_in[5];
    const float* bhh     = (const float*)d_in[6];
    const float* Wo      = (const float*)d_in[7];
    float* out           = (float*)d_out;

    gru_mma_kernel<<<NSEQ / 64, 128>>>(spatial, met, ctx, Wih, Whh, bih, bhh, Wo, out);
}

// round 11
// speedup vs baseline: 7.0806x; 1.3169x over previous
#include <cuda_runtime.h>
#include <cuda_fp16.h>
#include <cstdint>

// TemporalViewModel GRU, R9: warp-level mma.sync.m16n8k16 **fp16** path.
// Change vs R8: bf16 3-term split -> fp16 2-term. Activations (x, h) are
// single fp16 (11 mantissa bits, error 2^-11/step, random); weights stay
// 2-term fp16 hi+lo (2^-22, no systematic bias). MMA count per step drops
// 144 -> 96 (tensor-pipe busy floor ~95us -> ~63us). A-fragments lose their
// lo halves (-16 regs), h-repack is 8 cvts instead of 8 splits.

namespace {
constexpr int T_STEPS = 24;
constexpr int NSEQ    = 65536;       // B*X*Y
constexpr int S = 16, Mf = 8, Cf = 8;
}
typedef uint32_t u32;

// pack two fp32 -> f16x2 word, elem0 in LOW half (first PTX operand = high)
__device__ __forceinline__ u32 pkh(float e0, float e1) {
    u32 d; asm("cvt.rn.f16x2.f32 %0, %1, %2;" : "=r"(d) : "f"(e1), "f"(e0));
    return d;
}
// weight split: hi = rn(fp16), lo = rn(fp16) of residual (init-time only)
__device__ __forceinline__ void split2h(float x0, float x1, u32& hi, u32& lo) {
    __half h0 = __float2half_rn(x0), h1 = __float2half_rn(x1);
    hi = (u32)__half_as_ushort(h0) | ((u32)__half_as_ushort(h1) << 16);
    __half l0 = __float2half_rn(x0 - __half2float(h0));
    __half l1 = __float2half_rn(x1 - __half2float(h1));
    lo = (u32)__half_as_ushort(l0) | ((u32)__half_as_ushort(l1) << 16);
}
__device__ __forceinline__ float tanh_hw(float x) {
    float y; asm("tanh.approx.f32 %0, %1;" : "=f"(y) : "f"(x)); return y;
}
__device__ __forceinline__ float sigm_hw(float x) {
    return fmaf(0.5f, tanh_hw(0.5f * x), 0.5f);
}
__device__ __forceinline__ void mma16816(float* c, const u32* a, u32 b0, u32 b1) {
    asm volatile(
        "mma.sync.aligned.m16n8k16.row.col.f32.f16.f16.f32 "
        "{%0,%1,%2,%3}, {%4,%5,%6,%7}, {%8,%9}, {%0,%1,%2,%3};"
        : "+f"(c[0]), "+f"(c[1]), "+f"(c[2]), "+f"(c[3])
        : "r"(a[0]), "r"(a[1]), "r"(a[2]), "r"(a[3]), "r"(b0), "r"(b1));
}

__global__ void __launch_bounds__(128, 4)
gru_mma_kernel(const float* __restrict__ spatial,
               const float* __restrict__ met,
               const float* __restrict__ ctx,
               const float* __restrict__ Wih,   // (96, 32) row-major
               const float* __restrict__ Whh,   // (96, 32)
               const float* __restrict__ bih,   // (96,)
               const float* __restrict__ bhh,   // (96,)
               const float* __restrict__ Wo,    // (32, 16)
               float* __restrict__ out)         // (N, 16)
{
    // B fragments in m16n8k16 fragment order: word idx (kc*12+nt)*64 + lane*2 + wi
    // nt 0..3 = r tiles, 4..7 = z tiles, 8..11 = n tiles.
    __shared__ __align__(16) u32 sBXh[1536], sBXl[1536];   // Wih^T frags hi/lo (fp16x2)
    __shared__ __align__(16) u32 sBHh[1536], sBHl[1536];   // Whh^T frags
    __shared__ __align__(16) u32 sBOh[256],  sBOl[256];    // Wo frags
    __shared__ __align__(8)  float sBr[32], sBz[32], sBnx[32], sBnh[32];

    const int tid = threadIdx.x;

    for (int w = tid; w < 1536; w += 128) {
        int f = w >> 6, r = w & 63, ln = r >> 1, wi = r & 1;
        int kc = f / 12, nt = f % 12;
        int g = ln >> 2, t = ln & 3;
        int n = nt * 8 + g;
        int k = kc * 16 + 2 * t + wi * 8;
        u32 hi, lo;
        split2h(Wih[n * 32 + k], Wih[n * 32 + k + 1], hi, lo);
        sBXh[w] = hi; sBXl[w] = lo;
        split2h(Whh[n * 32 + k], Whh[n * 32 + k + 1], hi, lo);
        sBHh[w] = hi; sBHl[w] = lo;
    }
    for (int w = tid; w < 256; w += 128) {
        int f = w >> 6, r = w & 63, ln = r >> 1, wi = r & 1;
        int kc = f >> 1, nt = f & 1;
        int g = ln >> 2, t = ln & 3;
        int n = nt * 8 + g;
        int k = kc * 16 + 2 * t + wi * 8;
        u32 hi, lo;
        split2h(Wo[k * 16 + n], Wo[(k + 1) * 16 + n], hi, lo);
        sBOh[w] = hi; sBOl[w] = lo;
    }
    if (tid < 32) {
        sBr[tid]  = bih[tid]      + bhh[tid];
        sBz[tid]  = bih[32 + tid] + bhh[32 + tid];
        sBnx[tid] = bih[64 + tid];
        sBnh[tid] = bhh[64 + tid];
    }
    __syncthreads();

    const int lane = tid & 31;
    const int g  = lane >> 2;
    const int tq = lane & 3;
    const int lane2 = lane * 2;

    const int warp_g = blockIdx.x * 4 + (tid >> 5);
    const int seq0 = warp_g * 16 + g;
    const int seq1 = seq0 + 8;

    const float* sp0 = spatial + (size_t)seq0 * S  + 2 * tq;
    const float* sp1 = spatial + (size_t)seq1 * S  + 2 * tq;
    const float* mp0 = met     + (size_t)seq0 * Mf + 2 * tq;
    const float* mp1 = met     + (size_t)seq1 * Mf + 2 * tq;
    const float* cp0 = ctx     + (size_t)seq0 * Cf + 2 * tq;
    const float* cp1 = ctx     + (size_t)seq1 * Cf + 2 * tq;

    float hC[4][4];
    u32 Ah[2][4] = {{0,0,0,0},{0,0,0,0}};   // h fragments, single fp16
    #pragma unroll
    for (int q = 0; q < 4; q++)
        #pragma unroll
        for (int i = 0; i < 4; i++) hC[q][i] = 0.f;

    #pragma unroll 1
    for (int t = 0; t < T_STEPS; t++) {
        // ---- x A-fragments straight from GMEM (single fp16) ----
        u32 Ax[2][4];
        {
            float2 v;
            v = *(const float2*)(sp0);     Ax[0][0] = pkh(v.x, v.y);
            v = *(const float2*)(sp1);     Ax[0][1] = pkh(v.x, v.y);
            v = *(const float2*)(sp0 + 8); Ax[0][2] = pkh(v.x, v.y);
            v = *(const float2*)(sp1 + 8); Ax[0][3] = pkh(v.x, v.y);
            v = *(const float2*)(mp0);     Ax[1][0] = pkh(v.x, v.y);
            v = *(const float2*)(mp1);     Ax[1][1] = pkh(v.x, v.y);
            v = *(const float2*)(cp0);     Ax[1][2] = pkh(v.x, v.y);
            v = *(const float2*)(cp1);     Ax[1][3] = pkh(v.x, v.y);
            sp0 += (size_t)NSEQ * S;  sp1 += (size_t)NSEQ * S;
            mp0 += (size_t)NSEQ * Mf; mp1 += (size_t)NSEQ * Mf;
            cp0 += (size_t)NSEQ * Cf; cp1 += (size_t)NSEQ * Cf;
        }

        float nn[4][4];   // r -> g -> n staging

        // ======== phase 1: r tiles (nt 0..3) ========
        {
            float acc[4][4];
            #pragma unroll
            for (int q = 0; q < 4; q++)
                #pragma unroll
                for (int i = 0; i < 4; i++) acc[q][i] = 0.f;
            #pragma unroll
            for (int kc = 0; kc < 2; kc++)
                #pragma unroll
                for (int nt = 0; nt < 4; nt++) {
                    int fo = (kc * 12 + nt) * 64 + lane2;
                    uint2 bh = *(const uint2*)&sBXh[fo];
                    uint2 bl = *(const uint2*)&sBXl[fo];
                    mma16816(acc[nt], Ax[kc], bh.x, bh.y);
                    mma16816(acc[nt], Ax[kc], bl.x, bl.y);
                    uint2 ch = *(const uint2*)&sBHh[fo];
                    uint2 cl = *(const uint2*)&sBHl[fo];
                    mma16816(acc[nt], Ah[kc], ch.x, ch.y);
                    mma16816(acc[nt], Ah[kc], cl.x, cl.y);
                }
            #pragma unroll
            for (int q = 0; q < 4; q++) {
                const float2 brv = ((const float2*)sBr)[4 * q + tq];
                #pragma unroll
                for (int i = 0; i < 4; i++)
                    nn[q][i] = sigm_hw(acc[q][i] + ((i & 1) ? brv.y : brv.x));
            }
        }

        // ======== phase 2: n_h tiles (nt 8..11), consume r ========
        {
            float acc[4][4];
            #pragma unroll
            for (int q = 0; q < 4; q++)
                #pragma unroll
                for (int i = 0; i < 4; i++) acc[q][i] = 0.f;
            #pragma unroll
            for (int kc = 0; kc < 2; kc++)
                #pragma unroll
                for (int nt = 0; nt < 4; nt++) {
                    int fo = (kc * 12 + 8 + nt) * 64 + lane2;
                    uint2 ch = *(const uint2*)&sBHh[fo];
                    uint2 cl = *(const uint2*)&sBHl[fo];
                    mma16816(acc[nt], Ah[kc], ch.x, ch.y);
                    mma16816(acc[nt], Ah[kc], cl.x, cl.y);
                }
            // g = bnx + r * (acc + bnh)
            #pragma unroll
            for (int q = 0; q < 4; q++) {
                const float2 bnxv = ((const float2*)sBnx)[4 * q + tq];
                const float2 bnhv = ((const float2*)sBnh)[4 * q + tq];
                #pragma unroll
                for (int i = 0; i < 4; i++) {
                    const float bx = (i & 1) ? bnxv.y : bnxv.x;
                    const float bb = (i & 1) ? bnhv.y : bnhv.x;
                    nn[q][i] = fmaf(nn[q][i], acc[q][i] + bb, bx);
                }
            }
        }

        // ======== phase 3: n_x tiles accumulate directly into g ========
        #pragma unroll
        for (int kc = 0; kc < 2; kc++)
            #pragma unroll
            for (int nt = 0; nt < 4; nt++) {
                int fo = (kc * 12 + 8 + nt) * 64 + lane2;
                uint2 bh = *(const uint2*)&sBXh[fo];
                uint2 bl = *(const uint2*)&sBXl[fo];
                mma16816(nn[nt], Ax[kc], bh.x, bh.y);
                mma16816(nn[nt], Ax[kc], bl.x, bl.y);
            }
        #pragma unroll
        for (int q = 0; q < 4; q++)
            #pragma unroll
            for (int i = 0; i < 4; i++) nn[q][i] = tanh_hw(nn[q][i]);

        // ======== phase 4: z tiles (nt 4..7) + combine ========
        {
            float acc[4][4];
            #pragma unroll
            for (int q = 0; q < 4; q++)
                #pragma unroll
                for (int i = 0; i < 4; i++) acc[q][i] = 0.f;
            #pragma unroll
            for (int kc = 0; kc < 2; kc++)
                #pragma unroll
                for (int nt = 0; nt < 4; nt++) {
                    int fo = (kc * 12 + 4 + nt) * 64 + lane2;
                    uint2 bh = *(const uint2*)&sBXh[fo];
                    uint2 bl = *(const uint2*)&sBXl[fo];
                    mma16816(acc[nt], Ax[kc], bh.x, bh.y);
                    mma16816(acc[nt], Ax[kc], bl.x, bl.y);
                    uint2 ch = *(const uint2*)&sBHh[fo];
                    uint2 cl = *(const uint2*)&sBHl[fo];
                    mma16816(acc[nt], Ah[kc], ch.x, ch.y);
                    mma16816(acc[nt], Ah[kc], cl.x, cl.y);
                }
            #pragma unroll
            for (int q = 0; q < 4; q++) {
                const float2 bzv = ((const float2*)sBz)[4 * q + tq];
                #pragma unroll
                for (int i = 0; i < 4; i++) {
                    float z = sigm_hw(acc[q][i] + ((i & 1) ? bzv.y : bzv.x));
                    hC[q][i] = fmaf(z, hC[q][i] - nn[q][i], nn[q][i]);
                }
            }
        }

        // ---- h C-fragments -> next step's A-fragments (single fp16 cvt) ----
        Ah[0][0] = pkh(hC[0][0], hC[0][1]);
        Ah[0][1] = pkh(hC[0][2], hC[0][3]);
        Ah[0][2] = pkh(hC[1][0], hC[1][1]);
        Ah[0][3] = pkh(hC[1][2], hC[1][3]);
        Ah[1][0] = pkh(hC[2][0], hC[2][1]);
        Ah[1][1] = pkh(hC[2][2], hC[2][3]);
        Ah[1][2] = pkh(hC[3][0], hC[3][1]);
        Ah[1][3] = pkh(hC[3][2], hC[3][3]);
    }

    // ---- output projection: out[16 x 16] = h @ Wo via 8 MMAs ----
    float co[2][4];
    #pragma unroll
    for (int nt = 0; nt < 2; nt++)
        #pragma unroll
        for (int i = 0; i < 4; i++) co[nt][i] = 0.f;
    #pragma unroll
    for (int kc = 0; kc < 2; kc++)
        #pragma unroll
        for (int nt = 0; nt < 2; nt++) {
            int fo = (kc * 2 + nt) * 64 + lane2;
            uint2 bh = *(const uint2*)&sBOh[fo];
            uint2 bl = *(const uint2*)&sBOl[fo];
            mma16816(co[nt], Ah[kc], bh.x, bh.y);
            mma16816(co[nt], Ah[kc], bl.x, bl.y);
        }
    #pragma unroll
    for (int nt = 0; nt < 2; nt++) {
        *(float2*)(out + (size_t)seq0 * 16 + nt * 8 + 2 * tq) = make_float2(co[nt][0], co[nt][1]);
        *(float2*)(out + (size_t)seq1 * 16 + nt * 8 + 2 * tq) = make_float2(co[nt][2], co[nt][3]);
    }
}

extern "C" void kernel_launch(void* const* d_in, const int* in_sizes, int n_in,
                              void* d_out, int out_size) {
    (void)in_sizes; (void)n_in; (void)out_size;
    const float* spatial = (const float*)d_in[0];
    const float* met     = (const float*)d_in[1];
    const float* ctx     = (const float*)d_in[2];
    const float* Wih     = (const float*)d_in[3];
    const float* Whh     = (const float*)d_in[4];
    const float* bih     = (const float*)d_in[5];
    const float* bhh     = (const float*)d_in[6];
    const float* Wo      = (const float*)d_in[7];
    float* out           = (float*)d_out;

    gru_mma_kernel<<<NSEQ / 64, 128>>>(spatial, met, ctx, Wih, Whh, bih, bhh, Wo, out);
}

// round 12
// speedup vs baseline: 8.1655x; 1.1532x over previous
#include <cuda_runtime.h>
#include <cuda_fp16.h>
#include <cstdint>

// TemporalViewModel GRU, R10: warp-level mma.sync.m16n8k16 fp16 path.
// vs R9: (1) x-side weights single fp16 (lo terms dropped; h-side keeps
// hi+lo since recurrent error compounds) -> 96 -> 72 MMAs/step.
// (2) Whh hi/lo fragments interleaved as uint4 so one LDS.128 feeds two MMAs.

namespace {
constexpr int T_STEPS = 24;
constexpr int NSEQ    = 65536;       // B*X*Y
constexpr int S = 16, Mf = 8, Cf = 8;
}
typedef uint32_t u32;

__device__ __forceinline__ u32 pkh(float e0, float e1) {
    u32 d; asm("cvt.rn.f16x2.f32 %0, %1, %2;" : "=r"(d) : "f"(e1), "f"(e0));
    return d;
}
__device__ __forceinline__ void split2h(float x0, float x1, u32& hi, u32& lo) {
    __half h0 = __float2half_rn(x0), h1 = __float2half_rn(x1);
    hi = (u32)__half_as_ushort(h0) | ((u32)__half_as_ushort(h1) << 16);
    __half l0 = __float2half_rn(x0 - __half2float(h0));
    __half l1 = __float2half_rn(x1 - __half2float(h1));
    lo = (u32)__half_as_ushort(l0) | ((u32)__half_as_ushort(l1) << 16);
}
__device__ __forceinline__ float tanh_hw(float x) {
    float y; asm("tanh.approx.f32 %0, %1;" : "=f"(y) : "f"(x)); return y;
}
__device__ __forceinline__ float sigm_hw(float x) {
    return fmaf(0.5f, tanh_hw(0.5f * x), 0.5f);
}
__device__ __forceinline__ void mma16816(float* c, const u32* a, u32 b0, u32 b1) {
    asm volatile(
        "mma.sync.aligned.m16n8k16.row.col.f32.f16.f16.f32 "
        "{%0,%1,%2,%3}, {%4,%5,%6,%7}, {%8,%9}, {%0,%1,%2,%3};"
        : "+f"(c[0]), "+f"(c[1]), "+f"(c[2]), "+f"(c[3])
        : "r"(a[0]), "r"(a[1]), "r"(a[2]), "r"(a[3]), "r"(b0), "r"(b1));
}

__global__ void __launch_bounds__(128, 4)
gru_mma_kernel(const float* __restrict__ spatial,
               const float* __restrict__ met,
               const float* __restrict__ ctx,
               const float* __restrict__ Wih,   // (96, 32) row-major
               const float* __restrict__ Whh,   // (96, 32)
               const float* __restrict__ bih,   // (96,)
               const float* __restrict__ bhh,   // (96,)
               const float* __restrict__ Wo,    // (32, 16)
               float* __restrict__ out)         // (N, 16)
{
    // x-weights: hi only, word idx (kc*12+nt)*64 + lane*2 + wi
    __shared__ __align__(16) u32 sBXh[1536];
    // h-weights: uint4-interleaved {hi_b0, hi_b1, lo_b0, lo_b1},
    // entry idx (kc*12+nt)*32 + lane
    __shared__ __align__(16) u32 sBH4[768 * 4];
    __shared__ __align__(16) u32 sBOh[256], sBOl[256];
    __shared__ __align__(8)  float sBr[32], sBz[32], sBnx[32], sBnh[32];

    const int tid = threadIdx.x;

    for (int w = tid; w < 1536; w += 128) {
        int f = w >> 6, r = w & 63, ln = r >> 1, wi = r & 1;
        int kc = f / 12, nt = f % 12;
        int g = ln >> 2, t = ln & 3;
        int n = nt * 8 + g;
        int k = kc * 16 + 2 * t + wi * 8;
        u32 hi, lo;
        split2h(Wih[n * 32 + k], Wih[n * 32 + k + 1], hi, lo);
        sBXh[w] = hi;                            // lo dropped (x-side single fp16)
        split2h(Whh[n * 32 + k], Whh[n * 32 + k + 1], hi, lo);
        int e = (kc * 12 + nt) * 32 + ln;
        sBH4[e * 4 + wi]     = hi;
        sBH4[e * 4 + 2 + wi] = lo;
    }
    for (int w = tid; w < 256; w += 128) {
        int f = w >> 6, r = w & 63, ln = r >> 1, wi = r & 1;
        int kc = f >> 1, nt = f & 1;
        int g = ln >> 2, t = ln & 3;
        int n = nt * 8 + g;
        int k = kc * 16 + 2 * t + wi * 8;
        u32 hi, lo;
        split2h(Wo[k * 16 + n], Wo[(k + 1) * 16 + n], hi, lo);
        sBOh[w] = hi; sBOl[w] = lo;
    }
    if (tid < 32) {
        sBr[tid]  = bih[tid]      + bhh[tid];
        sBz[tid]  = bih[32 + tid] + bhh[32 + tid];
        sBnx[tid] = bih[64 + tid];
        sBnh[tid] = bhh[64 + tid];
    }
    __syncthreads();

    const int lane = tid & 31;
    const int g  = lane >> 2;
    const int tq = lane & 3;
    const int lane2 = lane * 2;

    const int warp_g = blockIdx.x * 4 + (tid >> 5);
    const int seq0 = warp_g * 16 + g;
    const int seq1 = seq0 + 8;

    const float* sp0 = spatial + (size_t)seq0 * S  + 2 * tq;
    const float* sp1 = spatial + (size_t)seq1 * S  + 2 * tq;
    const float* mp0 = met     + (size_t)seq0 * Mf + 2 * tq;
    const float* mp1 = met     + (size_t)seq1 * Mf + 2 * tq;
    const float* cp0 = ctx     + (size_t)seq0 * Cf + 2 * tq;
    const float* cp1 = ctx     + (size_t)seq1 * Cf + 2 * tq;

    float hC[4][4];
    u32 Ah[2][4] = {{0,0,0,0},{0,0,0,0}};
    #pragma unroll
    for (int q = 0; q < 4; q++)
        #pragma unroll
        for (int i = 0; i < 4; i++) hC[q][i] = 0.f;

    #pragma unroll 1
    for (int t = 0; t < T_STEPS; t++) {
        // ---- x A-fragments straight from GMEM (single fp16) ----
        u32 Ax[2][4];
        {
            float2 v;
            v = *(const float2*)(sp0);     Ax[0][0] = pkh(v.x, v.y);
            v = *(const float2*)(sp1);     Ax[0][1] = pkh(v.x, v.y);
            v = *(const float2*)(sp0 + 8); Ax[0][2] = pkh(v.x, v.y);
            v = *(const float2*)(sp1 + 8); Ax[0][3] = pkh(v.x, v.y);
            v = *(const float2*)(mp0);     Ax[1][0] = pkh(v.x, v.y);
            v = *(const float2*)(mp1);     Ax[1][1] = pkh(v.x, v.y);
            v = *(const float2*)(cp0);     Ax[1][2] = pkh(v.x, v.y);
            v = *(const float2*)(cp1);     Ax[1][3] = pkh(v.x, v.y);
            sp0 += (size_t)NSEQ * S;  sp1 += (size_t)NSEQ * S;
            mp0 += (size_t)NSEQ * Mf; mp1 += (size_t)NSEQ * Mf;
            cp0 += (size_t)NSEQ * Cf; cp1 += (size_t)NSEQ * Cf;
        }

        float nn[4][4];   // r -> g -> n staging

        // ======== phase 1: r tiles (nt 0..3): x.hi + h.hi + h.lo ========
        {
            float acc[4][4];
            #pragma unroll
            for (int q = 0; q < 4; q++)
                #pragma unroll
                for (int i = 0; i < 4; i++) acc[q][i] = 0.f;
            #pragma unroll
            for (int kc = 0; kc < 2; kc++)
                #pragma unroll
                for (int nt = 0; nt < 4; nt++) {
                    uint2 bh = *(const uint2*)&sBXh[(kc * 12 + nt) * 64 + lane2];
                    mma16816(acc[nt], Ax[kc], bh.x, bh.y);
                    uint4 c4 = ((const uint4*)sBH4)[(kc * 12 + nt) * 32 + lane];
                    mma16816(acc[nt], Ah[kc], c4.x, c4.y);
                    mma16816(acc[nt], Ah[kc], c4.z, c4.w);
                }
            #pragma unroll
            for (int q = 0; q < 4; q++) {
                const float2 brv = ((const float2*)sBr)[4 * q + tq];
                #pragma unroll
                for (int i = 0; i < 4; i++)
                    nn[q][i] = sigm_hw(acc[q][i] + ((i & 1) ? brv.y : brv.x));
            }
        }

        // ======== phase 2: n_h tiles (nt 8..11), consume r ========
        {
            float acc[4][4];
            #pragma unroll
            for (int q = 0; q < 4; q++)
                #pragma unroll
                for (int i = 0; i < 4; i++) acc[q][i] = 0.f;
            #pragma unroll
            for (int kc = 0; kc < 2; kc++)
                #pragma unroll
                for (int nt = 0; nt < 4; nt++) {
                    uint4 c4 = ((const uint4*)sBH4)[(kc * 12 + 8 + nt) * 32 + lane];
                    mma16816(acc[nt], Ah[kc], c4.x, c4.y);
                    mma16816(acc[nt], Ah[kc], c4.z, c4.w);
                }
            // g = bnx + r * (acc + bnh)
            #pragma unroll
            for (int q = 0; q < 4; q++) {
                const float2 bnxv = ((const float2*)sBnx)[4 * q + tq];
                const float2 bnhv = ((const float2*)sBnh)[4 * q + tq];
                #pragma unroll
                for (int i = 0; i < 4; i++) {
                    const float bx = (i & 1) ? bnxv.y : bnxv.x;
                    const float bb = (i & 1) ? bnhv.y : bnhv.x;
                    nn[q][i] = fmaf(nn[q][i], acc[q][i] + bb, bx);
                }
            }
        }

        // ======== phase 3: n_x tiles accumulate into g (x.hi only) ========
        #pragma unroll
        for (int kc = 0; kc < 2; kc++)
            #pragma unroll
            for (int nt = 0; nt < 4; nt++) {
                uint2 bh = *(const uint2*)&sBXh[(kc * 12 + 8 + nt) * 64 + lane2];
                mma16816(nn[nt], Ax[kc], bh.x, bh.y);
            }
        #pragma unroll
        for (int q = 0; q < 4; q++)
            #pragma unroll
            for (int i = 0; i < 4; i++) nn[q][i] = tanh_hw(nn[q][i]);

        // ======== phase 4: z tiles (nt 4..7) + combine ========
        {
            float acc[4][4];
            #pragma unroll
            for (int q = 0; q < 4; q++)
                #pragma unroll
                for (int i = 0; i < 4; i++) acc[q][i] = 0.f;
            #pragma unroll
            for (int kc = 0; kc < 2; kc++)
                #pragma unroll
                for (int nt = 0; nt < 4; nt++) {
                    uint2 bh = *(const uint2*)&sBXh[(kc * 12 + 4 + nt) * 64 + lane2];
                    mma16816(acc[nt], Ax[kc], bh.x, bh.y);
                    uint4 c4 = ((const uint4*)sBH4)[(kc * 12 + 4 + nt) * 32 + lane];
                    mma16816(acc[nt], Ah[kc], c4.x, c4.y);
                    mma16816(acc[nt], Ah[kc], c4.z, c4.w);
                }
            #pragma unroll
            for (int q = 0; q < 4; q++) {
                const float2 bzv = ((const float2*)sBz)[4 * q + tq];
                #pragma unroll
                for (int i = 0; i < 4; i++) {
                    float z = sigm_hw(acc[q][i] + ((i & 1) ? bzv.y : bzv.x));
                    hC[q][i] = fmaf(z, hC[q][i] - nn[q][i], nn[q][i]);
                }
            }
        }

        // ---- h C-fragments -> next step's A-fragments (single fp16 cvt) ----
        Ah[0][0] = pkh(hC[0][0], hC[0][1]);
        Ah[0][1] = pkh(hC[0][2], hC[0][3]);
        Ah[0][2] = pkh(hC[1][0], hC[1][1]);
        Ah[0][3] = pkh(hC[1][2], hC[1][3]);
        Ah[1][0] = pkh(hC[2][0], hC[2][1]);
        Ah[1][1] = pkh(hC[2][2], hC[2][3]);
        Ah[1][2] = pkh(hC[3][0], hC[3][1]);
        Ah[1][3] = pkh(hC[3][2], hC[3][3]);
    }

    // ---- output projection: out[16 x 16] = h @ Wo via 8 MMAs (hi+lo) ----
    float co[2][4];
    #pragma unroll
    for (int nt = 0; nt < 2; nt++)
        #pragma unroll
        for (int i = 0; i < 4; i++) co[nt][i] = 0.f;
    #pragma unroll
    for (int kc = 0; kc < 2; kc++)
        #pragma unroll
        for (int nt = 0; nt < 2; nt++) {
            int fo = (kc * 2 + nt) * 64 + lane2;
            uint2 bh = *(const uint2*)&sBOh[fo];
            uint2 bl = *(const uint2*)&sBOl[fo];
            mma16816(co[nt], Ah[kc], bh.x, bh.y);
            mma16816(co[nt], Ah[kc], bl.x, bl.y);
        }
    #pragma unroll
    for (int nt = 0; nt < 2; nt++) {
        *(float2*)(out + (size_t)seq0 * 16 + nt * 8 + 2 * tq) = make_float2(co[nt][0], co[nt][1]);
        *(float2*)(out + (size_t)seq1 * 16 + nt * 8 + 2 * tq) = make_float2(co[nt][2], co[nt][3]);
    }
}

extern "C" void kernel_launch(void* const* d_in, const int* in_sizes, int n_in,
                              void* d_out, int out_size) {
    (void)in_sizes; (void)n_in; (void)out_size;
    const float* spatial = (const float*)d_in[0];
    const float* met     = (const float*)d_in[1];
    const float* ctx     = (const float*)d_in[2];
    const float* Wih     = (const float*)d_in[3];
    const float* Whh     = (const float*)d_in[4];
    const float* bih     = (const float*)d_in[5];
    const float* bhh     = (const float*)d_in[6];
    const float* Wo      = (const float*)d_in[7];
    float* out           = (float*)d_out;

    gru_mma_kernel<<<NSEQ / 64, 128>>>(spatial, met, ctx, Wih, Whh, bih, bhh, Wo, out);
}

// round 13
// speedup vs baseline: 9.0510x; 1.1084x over previous
#include <cuda_runtime.h>
#include <cuda_fp16.h>
#include <cstdint>

// TemporalViewModel GRU, R11: warp-level mma.sync.m16n8k16 fp16 path.
// vs R10: (1) cp.async double-buffered prefetch of x_{t+1} into SMEM kills the
// per-step ~500cyc LDG latency bubble (each thread reads back only its own
// slots -> no extra syncs, no register growth). (2) z-gate h-weights single
// fp16 (r keeps hi+lo: feeds tanh product; n keeps hi+lo: feeds h directly);
// 72 -> 64 MMAs/step.

namespace {
constexpr int T_STEPS = 24;
constexpr int NSEQ    = 65536;       // B*X*Y
constexpr int S = 16, Mf = 8, Cf = 8;
}
typedef uint32_t u32;

__device__ __forceinline__ u32 pkh(float e0, float e1) {
    u32 d; asm("cvt.rn.f16x2.f32 %0, %1, %2;" : "=r"(d) : "f"(e1), "f"(e0));
    return d;
}
__device__ __forceinline__ void split2h(float x0, float x1, u32& hi, u32& lo) {
    __half h0 = __float2half_rn(x0), h1 = __float2half_rn(x1);
    hi = (u32)__half_as_ushort(h0) | ((u32)__half_as_ushort(h1) << 16);
    __half l0 = __float2half_rn(x0 - __half2float(h0));
    __half l1 = __float2half_rn(x1 - __half2float(h1));
    lo = (u32)__half_as_ushort(l0) | ((u32)__half_as_ushort(l1) << 16);
}
__device__ __forceinline__ float tanh_hw(float x) {
    float y; asm("tanh.approx.f32 %0, %1;" : "=f"(y) : "f"(x)); return y;
}
__device__ __forceinline__ float sigm_hw(float x) {
    return fmaf(0.5f, tanh_hw(0.5f * x), 0.5f);
}
__device__ __forceinline__ void mma16816(float* c, const u32* a, u32 b0, u32 b1) {
    asm volatile(
        "mma.sync.aligned.m16n8k16.row.col.f32.f16.f16.f32 "
        "{%0,%1,%2,%3}, {%4,%5,%6,%7}, {%8,%9}, {%0,%1,%2,%3};"
        : "+f"(c[0]), "+f"(c[1]), "+f"(c[2]), "+f"(c[3])
        : "r"(a[0]), "r"(a[1]), "r"(a[2]), "r"(a[3]), "r"(b0), "r"(b1));
}
__device__ __forceinline__ uint32_t smem_u32(const void* p) {
    uint32_t a;
    asm("{ .reg .u64 t; cvta.to.shared.u64 t, %1; cvt.u32.u64 %0, t; }"
        : "=r"(a) : "l"(p));
    return a;
}
#define CP_ASYNC8(sa, ga) asm volatile("cp.async.ca.shared.global [%0], [%1], 8;" :: "r"(sa), "l"(ga) : "memory")
#define CP_COMMIT()       asm volatile("cp.async.commit_group;" ::: "memory")
#define CP_WAIT1()        asm volatile("cp.async.wait_group 1;" ::: "memory")
#define CP_WAIT0()        asm volatile("cp.async.wait_group 0;" ::: "memory")

__global__ void __launch_bounds__(128, 4)
gru_mma_kernel(const float* __restrict__ spatial,
               const float* __restrict__ met,
               const float* __restrict__ ctx,
               const float* __restrict__ Wih,   // (96, 32) row-major
               const float* __restrict__ Whh,   // (96, 32)
               const float* __restrict__ bih,   // (96,)
               const float* __restrict__ bhh,   // (96,)
               const float* __restrict__ Wo,    // (32, 16)
               float* __restrict__ out)         // (N, 16)
{
    // x-weights hi only: word idx (kc*12+nt)*64 + lane*2 + wi
    __shared__ __align__(16) u32 sBXh[1536];
    // h-weights: r tiles uint4 {hi0,hi1,lo0,lo1}, z tiles uint2 {hi0,hi1},
    // n tiles uint4. frag idx (kc*4+nt)*32 + lane.
    __shared__ __align__(16) uint4 sBHr4[256];
    __shared__ __align__(16) uint2 sBHz2[256];
    __shared__ __align__(16) uint4 sBHn4[256];
    __shared__ __align__(16) u32 sBOh[256], sBOl[256];
    __shared__ __align__(8)  float sBr[32], sBz[32], sBnx[32], sBnh[32];
    // x prefetch double buffer: [stage][slot][tid] float2
    __shared__ __align__(16) float2 sX[2][8][128];

    const int tid = threadIdx.x;

    for (int w = tid; w < 1536; w += 128) {
        int f = w >> 6, r = w & 63, ln = r >> 1, wi = r & 1;
        int kc = f / 12, nt = f % 12;
        int g = ln >> 2, t = ln & 3;
        int n = nt * 8 + g;
        int k = kc * 16 + 2 * t + wi * 8;
        u32 hi, lo;
        split2h(Wih[n * 32 + k], Wih[n * 32 + k + 1], hi, lo);
        sBXh[w] = hi;
        split2h(Whh[n * 32 + k], Whh[n * 32 + k + 1], hi, lo);
        if (nt < 4) {
            u32* p = (u32*)&sBHr4[(kc * 4 + nt) * 32 + ln];
            p[wi] = hi; p[2 + wi] = lo;
        } else if (nt < 8) {
            u32* p = (u32*)&sBHz2[(kc * 4 + (nt - 4)) * 32 + ln];
            p[wi] = hi;
        } else {
            u32* p = (u32*)&sBHn4[(kc * 4 + (nt - 8)) * 32 + ln];
            p[wi] = hi; p[2 + wi] = lo;
        }
    }
    for (int w = tid; w < 256; w += 128) {
        int f = w >> 6, r = w & 63, ln = r >> 1, wi = r & 1;
        int kc = f >> 1, nt = f & 1;
        int g = ln >> 2, t = ln & 3;
        int n = nt * 8 + g;
        int k = kc * 16 + 2 * t + wi * 8;
        u32 hi, lo;
        split2h(Wo[k * 16 + n], Wo[(k + 1) * 16 + n], hi, lo);
        sBOh[w] = hi; sBOl[w] = lo;
    }
    if (tid < 32) {
        sBr[tid]  = bih[tid]      + bhh[tid];
        sBz[tid]  = bih[32 + tid] + bhh[32 + tid];
        sBnx[tid] = bih[64 + tid];
        sBnh[tid] = bhh[64 + tid];
    }
    __syncthreads();

    const int lane = tid & 31;
    const int g  = lane >> 2;
    const int tq = lane & 3;
    const int lane2 = lane * 2;

    const int warp_g = blockIdx.x * 4 + (tid >> 5);
    const int seq0 = warp_g * 16 + g;
    const int seq1 = seq0 + 8;

    const float* sp0 = spatial + (size_t)seq0 * S  + 2 * tq;
    const float* sp1 = spatial + (size_t)seq1 * S  + 2 * tq;
    const float* mp0 = met     + (size_t)seq0 * Mf + 2 * tq;
    const float* mp1 = met     + (size_t)seq1 * Mf + 2 * tq;
    const float* cp0 = ctx     + (size_t)seq0 * Cf + 2 * tq;
    const float* cp1 = ctx     + (size_t)seq1 * Cf + 2 * tq;

    const uint32_t sXb = smem_u32(&sX[0][0][0]) + tid * 8;
    // issue one step's 8 slots into stage st, then advance pointers
    #define ISSUE_X(st)                                                  \
        do {                                                             \
            uint32_t b = sXb + (st) * 8 * 128 * 8;                       \
            CP_ASYNC8(b + 0 * 1024, sp0);                                \
            CP_ASYNC8(b + 1 * 1024, sp1);                                \
            CP_ASYNC8(b + 2 * 1024, sp0 + 8);                            \
            CP_ASYNC8(b + 3 * 1024, sp1 + 8);                            \
            CP_ASYNC8(b + 4 * 1024, mp0);                                \
            CP_ASYNC8(b + 5 * 1024, mp1);                                \
            CP_ASYNC8(b + 6 * 1024, cp0);                                \
            CP_ASYNC8(b + 7 * 1024, cp1);                                \
            CP_COMMIT();                                                 \
            sp0 += (size_t)NSEQ * S;  sp1 += (size_t)NSEQ * S;           \
            mp0 += (size_t)NSEQ * Mf; mp1 += (size_t)NSEQ * Mf;          \
            cp0 += (size_t)NSEQ * Cf; cp1 += (size_t)NSEQ * Cf;          \
        } while (0)

    ISSUE_X(0);   // prefetch t = 0

    float hC[4][4];
    u32 Ah[2][4] = {{0,0,0,0},{0,0,0,0}};
    #pragma unroll
    for (int q = 0; q < 4; q++)
        #pragma unroll
        for (int i = 0; i < 4; i++) hC[q][i] = 0.f;

    #pragma unroll 1
    for (int t = 0; t < T_STEPS; t++) {
        const int st = t & 1;
        if (t + 1 < T_STEPS) { ISSUE_X((t + 1) & 1); CP_WAIT1(); }
        else                 { CP_WAIT0(); }

        // ---- x A-fragments from the prefetch buffer (own slots only) ----
        u32 Ax[2][4];
        {
            float2 v;
            v = sX[st][0][tid]; Ax[0][0] = pkh(v.x, v.y);
            v = sX[st][1][tid]; Ax[0][1] = pkh(v.x, v.y);
            v = sX[st][2][tid]; Ax[0][2] = pkh(v.x, v.y);
            v = sX[st][3][tid]; Ax[0][3] = pkh(v.x, v.y);
            v = sX[st][4][tid]; Ax[1][0] = pkh(v.x, v.y);
            v = sX[st][5][tid]; Ax[1][1] = pkh(v.x, v.y);
            v = sX[st][6][tid]; Ax[1][2] = pkh(v.x, v.y);
            v = sX[st][7][tid]; Ax[1][3] = pkh(v.x, v.y);
        }

        float nn[4][4];   // r -> g -> n staging

        // ======== phase 1: r tiles: x.hi + h.hi + h.lo ========
        {
            float acc[4][4];
            #pragma unroll
            for (int q = 0; q < 4; q++)
                #pragma unroll
                for (int i = 0; i < 4; i++) acc[q][i] = 0.f;
            #pragma unroll
            for (int kc = 0; kc < 2; kc++)
                #pragma unroll
                for (int nt = 0; nt < 4; nt++) {
                    uint2 bh = *(const uint2*)&sBXh[(kc * 12 + nt) * 64 + lane2];
                    mma16816(acc[nt], Ax[kc], bh.x, bh.y);
                    uint4 c4 = sBHr4[(kc * 4 + nt) * 32 + lane];
                    mma16816(acc[nt], Ah[kc], c4.x, c4.y);
                    mma16816(acc[nt], Ah[kc], c4.z, c4.w);
                }
            #pragma unroll
            for (int q = 0; q < 4; q++) {
                const float2 brv = ((const float2*)sBr)[4 * q + tq];
                #pragma unroll
                for (int i = 0; i < 4; i++)
                    nn[q][i] = sigm_hw(acc[q][i] + ((i & 1) ? brv.y : brv.x));
            }
        }

        // ======== phase 2: n_h tiles, consume r ========
        {
            float acc[4][4];
            #pragma unroll
            for (int q = 0; q < 4; q++)
                #pragma unroll
                for (int i = 0; i < 4; i++) acc[q][i] = 0.f;
            #pragma unroll
            for (int kc = 0; kc < 2; kc++)
                #pragma unroll
                for (int nt = 0; nt < 4; nt++) {
                    uint4 c4 = sBHn4[(kc * 4 + nt) * 32 + lane];
                    mma16816(acc[nt], Ah[kc], c4.x, c4.y);
                    mma16816(acc[nt], Ah[kc], c4.z, c4.w);
                }
            // g = bnx + r * (acc + bnh)
            #pragma unroll
            for (int q = 0; q < 4; q++) {
                const float2 bnxv = ((const float2*)sBnx)[4 * q + tq];
                const float2 bnhv = ((const float2*)sBnh)[4 * q + tq];
                #pragma unroll
                for (int i = 0; i < 4; i++) {
                    const float bx = (i & 1) ? bnxv.y : bnxv.x;
                    const float bb = (i & 1) ? bnhv.y : bnhv.x;
                    nn[q][i] = fmaf(nn[q][i], acc[q][i] + bb, bx);
                }
            }
        }

        // ======== phase 3: n_x tiles accumulate into g (x.hi only) ========
        #pragma unroll
        for (int kc = 0; kc < 2; kc++)
            #pragma unroll
            for (int nt = 0; nt < 4; nt++) {
                uint2 bh = *(const uint2*)&sBXh[(kc * 12 + 8 + nt) * 64 + lane2];
                mma16816(nn[nt], Ax[kc], bh.x, bh.y);
            }
        #pragma unroll
        for (int q = 0; q < 4; q++)
            #pragma unroll
            for (int i = 0; i < 4; i++) nn[q][i] = tanh_hw(nn[q][i]);

        // ======== phase 4: z tiles (x.hi + h.hi only) + combine ========
        {
            float acc[4][4];
            #pragma unroll
            for (int q = 0; q < 4; q++)
                #pragma unroll
                for (int i = 0; i < 4; i++) acc[q][i] = 0.f;
            #pragma unroll
            for (int kc = 0; kc < 2; kc++)
                #pragma unroll
                for (int nt = 0; nt < 4; nt++) {
                    uint2 bh = *(const uint2*)&sBXh[(kc * 12 + 4 + nt) * 64 + lane2];
                    mma16816(acc[nt], Ax[kc], bh.x, bh.y);
                    uint2 ch = sBHz2[(kc * 4 + nt) * 32 + lane];
                    mma16816(acc[nt], Ah[kc], ch.x, ch.y);
                }
            #pragma unroll
            for (int q = 0; q < 4; q++) {
                const float2 bzv = ((const float2*)sBz)[4 * q + tq];
                #pragma unroll
                for (int i = 0; i < 4; i++) {
                    float z = sigm_hw(acc[q][i] + ((i & 1) ? bzv.y : bzv.x));
                    hC[q][i] = fmaf(z, hC[q][i] - nn[q][i], nn[q][i]);
                }
            }
        }

        // ---- h C-fragments -> next step's A-fragments ----
        Ah[0][0] = pkh(hC[0][0], hC[0][1]);
        Ah[0][1] = pkh(hC[0][2], hC[0][3]);
        Ah[0][2] = pkh(hC[1][0], hC[1][1]);
        Ah[0][3] = pkh(hC[1][2], hC[1][3]);
        Ah[1][0] = pkh(hC[2][0], hC[2][1]);
        Ah[1][1] = pkh(hC[2][2], hC[2][3]);
        Ah[1][2] = pkh(hC[3][0], hC[3][1]);
        Ah[1][3] = pkh(hC[3][2], hC[3][3]);
    }

    // ---- output projection: out[16 x 16] = h @ Wo via 8 MMAs (hi+lo) ----
    float co[2][4];
    #pragma unroll
    for (int nt = 0; nt < 2; nt++)
        #pragma unroll
        for (int i = 0; i < 4; i++) co[nt][i] = 0.f;
    #pragma unroll
    for (int kc = 0; kc < 2; kc++)
        #pragma unroll
        for (int nt = 0; nt < 2; nt++) {
            int fo = (kc * 2 + nt) * 64 + lane2;
            uint2 bh = *(const uint2*)&sBOh[fo];
            uint2 bl = *(const uint2*)&sBOl[fo];
            mma16816(co[nt], Ah[kc], bh.x, bh.y);
            mma16816(co[nt], Ah[kc], bl.x, bl.y);
        }
    #pragma unroll
    for (int nt = 0; nt < 2; nt++) {
        *(float2*)(out + (size_t)seq0 * 16 + nt * 8 + 2 * tq) = make_float2(co[nt][0], co[nt][1]);
        *(float2*)(out + (size_t)seq1 * 16 + nt * 8 + 2 * tq) = make_float2(co[nt][2], co[nt][3]);
    }
}

extern "C" void kernel_launch(void* const* d_in, const int* in_sizes, int n_in,
                              void* d_out, int out_size) {
    (void)in_sizes; (void)n_in; (void)out_size;
    const float* spatial = (const float*)d_in[0];
    const float* met     = (const float*)d_in[1];
    const float* ctx     = (const float*)d_in[2];
    const float* Wih     = (const float*)d_in[3];
    const float* Whh     = (const float*)d_in[4];
    const float* bih     = (const float*)d_in[5];
    const float* bhh     = (const float*)d_in[6];
    const float* Wo      = (const float*)d_in[7];
    float* out           = (float*)d_out;

    gru_mma_kernel<<<NSEQ / 64, 128>>>(spatial, met, ctx, Wih, Whh, bih, bhh, Wo, out);
}